// round 14
// baseline (speedup 1.0000x reference)
#include <cuda_runtime.h>
#include <cuda_fp16.h>
#include <math.h>
#include <stdint.h>

// ---------------- problem constants ----------------
#define Bsz   4
#define Lsz   2048
#define DMsz  1024
#define EDsz  2048
#define SEGsz 256
#define NSEG  8
#define NLsz  2
#define DTRsz 64
#define DCsz  66   // DTR + N

// ---------------- fp32 scratch ----------------
__device__ float g_xz   [(size_t)Bsz*Lsz*2*EDsz];
__device__ float g_xs   [(size_t)Bsz*Lsz*EDsz];
__device__ float g_delta[(size_t)Bsz*Lsz*EDsz];
__device__ float g_dC   [(size_t)Bsz*Lsz*DCsz];
__device__ float g_y    [(size_t)Bsz*Lsz*EDsz];
__device__ float g_K    [(size_t)Bsz*SEGsz*EDsz];
__device__ float g_h3   [(size_t)Bsz*SEGsz*EDsz];
__device__ float g_Yf   [(size_t)Bsz*Lsz*EDsz];

// ---------------- fp16 operands ----------------
__device__ __half g_xnh [(size_t)Bsz*Lsz*DMsz];
__device__ __half g_inwh[(size_t)2*EDsz*DMsz];
__device__ __half g_xsh [(size_t)Bsz*Lsz*EDsz];
__device__ __half g_xpwh[(size_t)128*EDsz];
__device__ __half g_keh [(size_t)Bsz*SEGsz*EDsz];
__device__ __half g_k1wh[(size_t)3*EDsz*EDsz];
__device__ __half g_h1h [(size_t)Bsz*SEGsz*3*EDsz];
__device__ __half g_k2wh[(size_t)EDsz*3*EDsz];
__device__ __half g_h2h [(size_t)Bsz*SEGsz*EDsz];
__device__ __half g_k3wh[(size_t)EDsz*EDsz];
__device__ __half g_ygh [(size_t)Bsz*Lsz*EDsz];
__device__ __half g_owh [(size_t)DMsz*EDsz];
__device__ __half g_dft1h[2*SEGsz*SEGsz];     // [512][256] M x K row-major
__device__ __half g_dft2h[SEGsz*2*SEGsz];     // [256][512]
__device__ __half g_Xfh [(size_t)Bsz*NSEG*2*SEGsz*EDsz];
__device__ __half g_Zbh [(size_t)Bsz*NSEG*2*SEGsz*EDsz];

// ---------------- small helpers ----------------
__device__ __forceinline__ uint2 pack4h(float a, float b, float c, float d) {
    __half2 h0 = __floats2half2_rn(a, b), h1 = __floats2half2_rn(c, d);
    uint2 u; u.x = *(uint32_t*)&h0; u.y = *(uint32_t*)&h1; return u;
}
__device__ __forceinline__ uint4 pack8h(float4 a, float4 b) {
    __half2 h0 = __floats2half2_rn(a.x, a.y), h1 = __floats2half2_rn(a.z, a.w);
    __half2 h2 = __floats2half2_rn(b.x, b.y), h3 = __floats2half2_rn(b.z, b.w);
    uint4 u; u.x = *(uint32_t*)&h0; u.y = *(uint32_t*)&h1;
    u.z = *(uint32_t*)&h2; u.w = *(uint32_t*)&h3; return u;
}
__device__ __forceinline__ float blkSum(float v) {
    __shared__ float sh[32];
    __syncthreads();
    int lane = threadIdx.x & 31, w = threadIdx.x >> 5;
#pragma unroll
    for (int o = 16; o; o >>= 1) v += __shfl_down_sync(0xffffffffu, v, o);
    if (!lane) sh[w] = v;
    __syncthreads();
    if (w == 0) {
        v = (lane < (int)(blockDim.x >> 5)) ? sh[lane] : 0.f;
#pragma unroll
        for (int o = 16; o; o >>= 1) v += __shfl_down_sync(0xffffffffu, v, o);
        if (!lane) sh[0] = v;
    }
    __syncthreads();
    return sh[0];
}

// ---------------- mma / async primitives ----------------
__device__ __forceinline__ void mma16816(float* d, const uint32_t* a, uint32_t b0, uint32_t b1) {
    asm volatile(
        "mma.sync.aligned.m16n8k16.row.col.f32.f16.f16.f32 "
        "{%0,%1,%2,%3}, {%4,%5,%6,%7}, {%8,%9}, {%0,%1,%2,%3};\n"
        : "+f"(d[0]), "+f"(d[1]), "+f"(d[2]), "+f"(d[3])
        : "r"(a[0]), "r"(a[1]), "r"(a[2]), "r"(a[3]), "r"(b0), "r"(b1));
}
__device__ __forceinline__ void ldsm4(uint32_t* r, uint32_t addr) {
    asm volatile("ldmatrix.sync.aligned.m8n8.x4.shared.b16 {%0,%1,%2,%3}, [%4];\n"
        : "=r"(r[0]), "=r"(r[1]), "=r"(r[2]), "=r"(r[3]) : "r"(addr));
}
__device__ __forceinline__ void ldsm4t(uint32_t* r, uint32_t addr) {
    asm volatile("ldmatrix.sync.aligned.m8n8.x4.trans.shared.b16 {%0,%1,%2,%3}, [%4];\n"
        : "=r"(r[0]), "=r"(r[1]), "=r"(r[2]), "=r"(r[3]) : "r"(addr));
}
__device__ __forceinline__ void cpa16(uint32_t dst, const void* src) {
    asm volatile("cp.async.cg.shared.global [%0], [%1], 16;\n" :: "r"(dst), "l"(src));
}
__device__ __forceinline__ void cpa_commit() { asm volatile("cp.async.commit_group;\n" ::: "memory"); }
template<int N> __device__ __forceinline__ void cpa_wait() {
    asm volatile("cp.async.wait_group %0;\n" :: "n"(N) : "memory");
}

// ================= single-fp16 mma.sync NT GEMM =================
// D = A(MxK) @ B(NxK)^T, fp16 inputs, fp32 accum.
// EPI: 0 none, 1 bias+relu, 2 relu, 4 C += result.  PAIR: emit fp16 output.
#define TS_STAGE 16384
template<int EPI, bool PAIR>
__global__ __launch_bounds__(256) void ts_gemm_k(
    const __half* __restrict__ Ahg, const __half* __restrict__ Bhg,
    float* __restrict__ C, __half* __restrict__ Oh,
    int lda, int ldb, int ldc, int Nn, int K, const float* __restrict__ bias)
{
    __shared__ __align__(16) char sm[2 * TS_STAGE];
    const int tid = threadIdx.x;
    const int lane = tid & 31, wid = tid >> 5;
    const int wm = wid & 1, wn = wid >> 1;
    const int m0 = blockIdx.y * 128, n0 = blockIdx.x * 128;

    float acc[4][4][4];
#pragma unroll
    for (int i = 0; i < 4; i++)
#pragma unroll
        for (int j = 0; j < 4; j++)
#pragma unroll
            for (int q = 0; q < 4; q++) acc[i][j][q] = 0.f;

    const uint32_t smBase = (uint32_t)__cvta_generic_to_shared(sm);
    const int frow0 = tid >> 2;
    const int fc    = tid & 3;
    auto fill = [&](int k0, int st) {
        const uint32_t base = smBase + st * TS_STAGE;
#pragma unroll
        for (int i = 0; i < 2; i++) {
            int row = frow0 + i * 64;
            uint32_t off = (uint32_t)(row * 64 + fc * 16);
            uint32_t dsw = off ^ ((off >> 3) & 0x30);
            cpa16(base +        dsw, Ahg + (size_t)(m0 + row) * lda + k0 + fc * 8);
            cpa16(base + 8192 + dsw, Bhg + (size_t)(n0 + row) * ldb + k0 + fc * 8);
        }
        cpa_commit();
    };

    const int aRow = wm * 64 + (lane & 15);
    const int aCh  = (lane >> 4);
    const int bRow = wn * 32 + (lane & 7) + ((lane & 16) >> 1);
    const int bCh  = ((lane & 8) >> 3);

    const int kt = K >> 5;
    fill(0, 0);
    for (int t = 0; t < kt; t++) {
        if (t + 1 < kt) { fill((t + 1) << 5, (t + 1) & 1); cpa_wait<1>(); }
        else            { cpa_wait<0>(); }
        __syncthreads();
        const uint32_t base = smBase + (t & 1) * TS_STAGE;
#pragma unroll
        for (int ks = 0; ks < 2; ks++) {
            uint32_t bh[2][4];
#pragma unroll
            for (int nt2 = 0; nt2 < 2; nt2++) {
                uint32_t off = (uint32_t)((bRow + nt2 * 16) * 64 + (bCh + ks * 2) * 16);
                uint32_t dsw = off ^ ((off >> 3) & 0x30);
                ldsm4(bh[nt2], base + 8192 + dsw);
            }
#pragma unroll
            for (int mt = 0; mt < 4; mt++) {
                uint32_t off = (uint32_t)((aRow + mt * 16) * 64 + (aCh + ks * 2) * 16);
                uint32_t dsw = off ^ ((off >> 3) & 0x30);
                uint32_t ah[4];
                ldsm4(ah, base + dsw);
#pragma unroll
                for (int n8 = 0; n8 < 4; n8++)
                    mma16816(acc[mt][n8], ah, bh[n8 >> 1][(n8 & 1) * 2], bh[n8 >> 1][(n8 & 1) * 2 + 1]);
            }
        }
        __syncthreads();
    }

    const int g = lane >> 2, cc = (lane & 3) * 2;
#pragma unroll
    for (int mt = 0; mt < 4; mt++) {
        long long m = m0 + wm * 64 + mt * 16 + g;
#pragma unroll
        for (int n8 = 0; n8 < 4; n8++) {
            int col = n0 + wn * 32 + n8 * 8 + cc;
            if (col >= Nn) continue;
            float* a4 = acc[mt][n8];
            float2 v0 = make_float2(a4[0], a4[1]);
            float2 v1 = make_float2(a4[2], a4[3]);
            if (EPI == 1) {
                float b0 = bias[col], b1 = bias[col + 1];
                v0.x = fmaxf(v0.x + b0, 0.f); v0.y = fmaxf(v0.y + b1, 0.f);
                v1.x = fmaxf(v1.x + b0, 0.f); v1.y = fmaxf(v1.y + b1, 0.f);
            } else if (EPI == 2) {
                v0.x = fmaxf(v0.x, 0.f); v0.y = fmaxf(v0.y, 0.f);
                v1.x = fmaxf(v1.x, 0.f); v1.y = fmaxf(v1.y, 0.f);
            }
            if (PAIR) {
                *(__half2*)(Oh + m * ldc + col)       = __floats2half2_rn(v0.x, v0.y);
                *(__half2*)(Oh + (m + 8) * ldc + col) = __floats2half2_rn(v1.x, v1.y);
            } else {
                float* p0 = C + m * ldc + col;
                float* p1 = C + (m + 8) * ldc + col;
                if (EPI == 4) {
                    float2 o0 = *(float2*)p0, o1 = *(float2*)p1;
                    v0.x += o0.x; v0.y += o0.y; v1.x += o1.x; v1.y += o1.y;
                }
                *(float2*)p0 = v0;
                *(float2*)p1 = v1;
            }
        }
    }
}

// ================= fp16 NN GEMM (FDU): C = A(MxK) @ B(KxN) =================
// A half row-major (shared across batch), B half row-major [K][N] (batched).
// HOUT: emit half output; else fp32.
#define NN_BROW 272                         // 136 halves padded B row
#define NN_STAGE (8192 + 32 * NN_BROW)      // A 8KB + B 8.5KB
template<bool HOUT>
__global__ __launch_bounds__(256) void tgemm_nnh_k(
    const __half* __restrict__ A, int lda,
    const __half* __restrict__ Bm, int ldb, long long sB,
    float* __restrict__ C, __half* __restrict__ Ch, int ldc, long long sC,
    int K)
{
    __shared__ __align__(16) char sm[2 * NN_STAGE];
    const int bz = blockIdx.z;
    Bm += (long long)bz * sB;
    const int m0 = blockIdx.y * 128, n0 = blockIdx.x * 128;
    const int tid = threadIdx.x;
    const int lane = tid & 31, wid = tid >> 5;
    const int wm = wid & 1, wn = wid >> 1;

    float acc[4][4][4];
#pragma unroll
    for (int i = 0; i < 4; i++)
#pragma unroll
        for (int j = 0; j < 4; j++)
#pragma unroll
            for (int q = 0; q < 4; q++) acc[i][j][q] = 0.f;

    const uint32_t smBase = (uint32_t)__cvta_generic_to_shared(sm);
    const int frow0 = tid >> 2;      // A rows
    const int fc    = tid & 3;
    const int bc2   = tid & 15;      // B: 16B chunk along n
    const int brow0 = tid >> 4;      // B rows (k), +16
    auto fill = [&](int k0, int st) {
        const uint32_t base = smBase + st * NN_STAGE;
#pragma unroll
        for (int i = 0; i < 2; i++) {
            int row = frow0 + i * 64;
            uint32_t off = (uint32_t)(row * 64 + fc * 16);
            uint32_t dsw = off ^ ((off >> 3) & 0x30);
            cpa16(base + dsw, A + (size_t)(m0 + row) * lda + k0 + fc * 8);
        }
#pragma unroll
        for (int i = 0; i < 2; i++) {
            int krow = brow0 + i * 16;
            cpa16(base + 8192 + krow * NN_BROW + bc2 * 16,
                  Bm + (size_t)(k0 + krow) * ldb + n0 + bc2 * 8);
        }
        cpa_commit();
    };

    const int aRow = wm * 64 + (lane & 15);
    const int aCh  = (lane >> 4);
    // B trans-ldmatrix lane mapping
    const int bg = lane >> 3;
    const int bRowL = (bg & 1) * 8 + (lane & 7);    // + ks*16
    const int bColL = (bg >> 1) * 8;                // + wn*32 + j*16

    const int kt = K >> 5;
    fill(0, 0);
    for (int t = 0; t < kt; t++) {
        if (t + 1 < kt) { fill((t + 1) << 5, (t + 1) & 1); cpa_wait<1>(); }
        else            { cpa_wait<0>(); }
        __syncthreads();
        const uint32_t base = smBase + (t & 1) * NN_STAGE;
#pragma unroll
        for (int ks = 0; ks < 2; ks++) {
            uint32_t bh[2][4];
#pragma unroll
            for (int j = 0; j < 2; j++) {
                uint32_t addr = base + 8192 + (ks * 16 + bRowL) * NN_BROW
                              + (wn * 32 + j * 16 + bColL) * 2;
                ldsm4t(bh[j], addr);
            }
#pragma unroll
            for (int mt = 0; mt < 4; mt++) {
                uint32_t off = (uint32_t)((aRow + mt * 16) * 64 + (aCh + ks * 2) * 16);
                uint32_t dsw = off ^ ((off >> 3) & 0x30);
                uint32_t ah[4];
                ldsm4(ah, base + dsw);
#pragma unroll
                for (int n8 = 0; n8 < 4; n8++)
                    mma16816(acc[mt][n8], ah, bh[n8 >> 1][(n8 & 1) * 2], bh[n8 >> 1][(n8 & 1) * 2 + 1]);
            }
        }
        __syncthreads();
    }

    const int g = lane >> 2, cc = (lane & 3) * 2;
#pragma unroll
    for (int mt = 0; mt < 4; mt++) {
        long long m = m0 + wm * 64 + mt * 16 + g;
#pragma unroll
        for (int n8 = 0; n8 < 4; n8++) {
            int col = n0 + wn * 32 + n8 * 8 + cc;
            float* a4 = acc[mt][n8];
            if (HOUT) {
                __half* p = Ch + (long long)bz * sC + m * ldc + col;
                *(__half2*)p                = __floats2half2_rn(a4[0], a4[1]);
                *(__half2*)(p + 8LL * ldc)  = __floats2half2_rn(a4[2], a4[3]);
            } else {
                float* p = C + (long long)bz * sC + m * ldc + col;
                *(float2*)p               = make_float2(a4[0], a4[1]);
                *(float2*)(p + 8LL * ldc) = make_float2(a4[2], a4[3]);
            }
        }
    }
}

// ---------------- DFT table init (half) ----------------
__global__ void dft_init_k() {
    int idx = blockIdx.x * 256 + threadIdx.x;
    int t = idx & 255, k = idx >> 8;
    int p = (k * t) & 255;
    float ang = 6.283185307179586f * (float)p * (1.0f / 256.0f);
    float s, c;
    sincosf(ang, &s, &c);
    g_dft1h[k * 256 + t]         = __float2half_rn(c);
    g_dft1h[(k + 256) * 256 + t] = __float2half_rn(-s);
    g_dft2h[t * 512 + k]         = __float2half_rn(c  * (1.0f / 256.0f));
    g_dft2h[t * 512 + 256 + k]   = __float2half_rn(-s * (1.0f / 256.0f));
}

// ---------------- weight convert (fp32 -> fp16), 8 elems/thread ----------------
__global__ void wconv_k(const float* __restrict__ src, __half* __restrict__ dh, int n8) {
    int i = blockIdx.x * 256 + threadIdx.x;
    if (i >= n8) return;
    const float4* s = (const float4*)src + (size_t)i * 2;
    *((uint4*)dh + i) = pack8h(s[0], s[1]);
}
__global__ void xppad_k(const float* __restrict__ src, __half* __restrict__ dh) {
    int i = blockIdx.x * 256 + threadIdx.x;
    int g0 = i * 8;
    int row = g0 >> 11, col = g0 & (EDsz - 1);
    float4 a = make_float4(0, 0, 0, 0), b = a;
    if (row < DCsz) {
        a = *(const float4*)(src + (size_t)row * EDsz + col);
        b = *(const float4*)(src + (size_t)row * EDsz + col + 4);
    }
    *((uint4*)dh + i) = pack8h(a, b);
}

// ---------------- RMSNorm -> fp16 ----------------
__global__ void rmsnorm_k(const float* __restrict__ h, const float* __restrict__ w,
                          __half* __restrict__ oh) {
    size_t base = (size_t)blockIdx.x * DMsz;
    int tid = threadIdx.x;
    float4 v = *((const float4*)(h + base) + tid);
    float s = v.x * v.x + v.y * v.y + v.z * v.z + v.w * v.w;
    s = blkSum(s);
    float r = rsqrtf(s * (1.0f / DMsz) + 1e-5f);
    float4 w4 = *((const float4*)w + tid);
    *((uint2*)(oh + base) + tid) = pack4h(v.x * r * w4.x, v.y * r * w4.y,
                                          v.z * r * w4.z, v.w * r * w4.w);
}

// ---------------- fused double depthwise conv (k=2) + SiLU (x4) ----------------
__global__ void conv_silu_k(const float* __restrict__ xz,
                            const float* __restrict__ c1w, const float* __restrict__ c1b,
                            const float* __restrict__ c2w, const float* __restrict__ c2b,
                            float* __restrict__ xs, __half* __restrict__ xsh) {
    size_t idx = (size_t)blockIdx.x * 256 + threadIdx.x;
    size_t g0 = idx * 4;
    int e = (int)(g0 & (EDsz - 1));
    int l = (int)((g0 >> 11) & (Lsz - 1));
    int b = (int)(g0 >> 22);
    const float* base = xz + (size_t)(b * Lsz) * (2 * EDsz) + e;
    float4 x2 = *(const float4*)(base + (size_t)l * (2 * EDsz));
    float4 x1 = (l >= 1) ? *(const float4*)(base + (size_t)(l - 1) * (2 * EDsz)) : make_float4(0,0,0,0);
    float4 x0 = (l >= 2) ? *(const float4*)(base + (size_t)(l - 2) * (2 * EDsz)) : make_float4(0,0,0,0);
    float4 w1a = *(const float4*)(c1w + e * 2);
    float4 w1b = *(const float4*)(c1w + e * 2 + 4);
    float4 w2a = *(const float4*)(c2w + e * 2);
    float4 w2b = *(const float4*)(c2w + e * 2 + 4);
    float4 b1 = *(const float4*)(c1b + e);
    float4 b2 = *(const float4*)(c2b + e);
    float r[4];
    {
        float X0[4] = {x0.x, x0.y, x0.z, x0.w};
        float X1[4] = {x1.x, x1.y, x1.z, x1.w};
        float X2[4] = {x2.x, x2.y, x2.z, x2.w};
        float W10[4] = {w1a.x, w1a.z, w1b.x, w1b.z};
        float W11[4] = {w1a.y, w1a.w, w1b.y, w1b.w};
        float W20[4] = {w2a.x, w2a.z, w2b.x, w2b.z};
        float W21[4] = {w2a.y, w2a.w, w2b.y, w2b.w};
        float B1[4] = {b1.x, b1.y, b1.z, b1.w};
        float B2[4] = {b2.x, b2.y, b2.z, b2.w};
#pragma unroll
        for (int j = 0; j < 4; j++) {
            float y1a = (l >= 1) ? (B1[j] + X0[j] * W10[j] + X1[j] * W11[j]) : 0.f;
            float y1b = B1[j] + X1[j] * W10[j] + X2[j] * W11[j];
            float y2 = B2[j] + y1a * W20[j] + y1b * W21[j];
            r[j] = y2 / (1.f + __expf(-y2));
        }
    }
    *(float4*)(xs + g0) = make_float4(r[0], r[1], r[2], r[3]);
    *(uint2*)(xsh + g0) = pack4h(r[0], r[1], r[2], r[3]);
}

// ---------------- SIMT fp32 GEMM (delta only: bias+softplus) ----------------
__global__ __launch_bounds__(256) void gemm_sp_k(
    const float* __restrict__ A, int lda,
    const float* __restrict__ Bm, int ldb,
    float* __restrict__ C, int ldc,
    int N, int K, const float* __restrict__ bias)
{
    __shared__ float As[16][128];
    __shared__ float Bs[16][132];
    const int m0 = blockIdx.y * 128, n0 = blockIdx.x * 128;
    const int tid = threadIdx.x;
    const int tx = tid & 15, ty = tid >> 4;
    float acc[8][8];
#pragma unroll
    for (int i = 0; i < 8; i++)
#pragma unroll
        for (int j = 0; j < 8; j++) acc[i][j] = 0.f;
    const bool a4 = ((lda & 3) == 0);

    for (int k0 = 0; k0 < K; k0 += 16) {
        {
            int r = tid >> 2, c4 = (tid & 3) << 2;
#pragma unroll
            for (int rr = 0; rr < 2; rr++) {
                int row = r + rr * 64;
                const float* p = A + (long long)(m0 + row) * lda + (k0 + c4);
                float4 v;
                if (a4) v = *(const float4*)p;
                else { v.x = p[0]; v.y = p[1]; v.z = p[2]; v.w = p[3]; }
                As[c4 + 0][row] = v.x; As[c4 + 1][row] = v.y;
                As[c4 + 2][row] = v.z; As[c4 + 3][row] = v.w;
            }
        }
        {
            int r = tid >> 2, c4 = (tid & 3) << 2;
#pragma unroll
            for (int rr = 0; rr < 2; rr++) {
                int row = r + rr * 64;
                float4 v = make_float4(0.f, 0.f, 0.f, 0.f);
                if (n0 + row < N) {
                    const float* p = Bm + (long long)(n0 + row) * ldb + (k0 + c4);
                    v.x = p[0]; v.y = p[1]; v.z = p[2]; v.w = p[3];
                }
                Bs[c4 + 0][row] = v.x; Bs[c4 + 1][row] = v.y;
                Bs[c4 + 2][row] = v.z; Bs[c4 + 3][row] = v.w;
            }
        }
        __syncthreads();
#pragma unroll
        for (int kk = 0; kk < 16; kk++) {
            float a[8], b[8];
            *(float4*)&a[0] = *(const float4*)&As[kk][ty * 8];
            *(float4*)&a[4] = *(const float4*)&As[kk][ty * 8 + 4];
            *(float4*)&b[0] = *(const float4*)&Bs[kk][tx * 8];
            *(float4*)&b[4] = *(const float4*)&Bs[kk][tx * 8 + 4];
#pragma unroll
            for (int i = 0; i < 8; i++)
#pragma unroll
                for (int j = 0; j < 8; j++)
                    acc[i][j] = fmaf(a[i], b[j], acc[i][j]);
        }
        __syncthreads();
    }
#pragma unroll
    for (int ii = 0; ii < 8; ii++) {
        long long m = m0 + ty * 8 + ii;
        float* Crow = C + m * (long long)ldc;
#pragma unroll
        for (int jj = 0; jj < 8; jj++) {
            int n = n0 + tx * 8 + jj;
            if (n >= N) continue;
            float v = acc[ii][jj] + bias[n];
            Crow[n] = (v > 20.f) ? v : log1pf(expf(v));
        }
    }
}

// ---------------- Kerr (s=0 only): softsign(xg^2) -> fp16 (x4) ----------------
__global__ void kerr_k(const float* __restrict__ xs, __half* __restrict__ kh, int s0) {
    size_t idx = (size_t)blockIdx.x * 256 + threadIdx.x;
    size_t g0 = idx * 4;
    int e = (int)(g0 & (EDsz - 1));
    int t = (int)((g0 >> 11) & (SEGsz - 1));
    int b = (int)(g0 >> 19);
    float4 xg = *(const float4*)(xs + ((size_t)(b * Lsz + s0 + t)) * EDsz + e);
    float r[4];
    float dx[4] = {xg.x, xg.y, xg.z, xg.w};
#pragma unroll
    for (int j = 0; j < 4; j++) { float d = dx[j] * dx[j]; r[j] = d / (1.f + d); }
    *(uint2*)(kh + g0) = pack4h(r[0], r[1], r[2], r[3]);
}

// ---------------- LayerNorm(h3) -> Knew; K = (1-a)K + a*Knew (x8, first flag) ---
__global__ void kup_k(const float* __restrict__ h3,
                      const float* __restrict__ lng, const float* __restrict__ lnb,
                      const float* __restrict__ kal, float* __restrict__ K, int first) {
    size_t base = (size_t)blockIdx.x * EDsz;
    int e0 = threadIdx.x * 8;
    float4 va = *(const float4*)(h3 + base + e0);
    float4 vb = *(const float4*)(h3 + base + e0 + 4);
    float v[8] = {va.x, va.y, va.z, va.w, vb.x, vb.y, vb.z, vb.w};
    float s = 0.f;
#pragma unroll
    for (int j = 0; j < 8; j++) s += v[j];
    s = blkSum(s);
    float mu = s * (1.0f / EDsz);
    float q = 0.f;
#pragma unroll
    for (int j = 0; j < 8; j++) { float d = v[j] - mu; q += d * d; }
    q = blkSum(q);
    float rstd = rsqrtf(q * (1.0f / EDsz) + 1e-5f);
    float4 ga = *(const float4*)(lng + e0), gb = *(const float4*)(lng + e0 + 4);
    float4 ba = *(const float4*)(lnb + e0), bb = *(const float4*)(lnb + e0 + 4);
    float4 aa = *(const float4*)(kal + e0), ab = *(const float4*)(kal + e0 + 4);
    float kv[8] = {0, 0, 0, 0, 0, 0, 0, 0};
    if (!first) {
        float4 ka = *(const float4*)(K + base + e0), kb = *(const float4*)(K + base + e0 + 4);
        kv[0] = ka.x; kv[1] = ka.y; kv[2] = ka.z; kv[3] = ka.w;
        kv[4] = kb.x; kv[5] = kb.y; kv[6] = kb.z; kv[7] = kb.w;
    }
    float gv[8] = {ga.x, ga.y, ga.z, ga.w, gb.x, gb.y, gb.z, gb.w};
    float bv[8] = {ba.x, ba.y, ba.z, ba.w, bb.x, bb.y, bb.z, bb.w};
    float av2[8] = {aa.x, aa.y, aa.z, aa.w, ab.x, ab.y, ab.z, ab.w};
#pragma unroll
    for (int j = 0; j < 8; j++) {
        float kn = gv[j] * (v[j] - mu) * rstd + bv[j];
        float a = fminf(fmaxf(av2[j], 0.01f), 0.99f);
        kv[j] = (1.f - a) * kv[j] + a * kn;
    }
    *(float4*)(K + base + e0)     = make_float4(kv[0], kv[1], kv[2], kv[3]);
    *(float4*)(K + base + e0 + 4) = make_float4(kv[4], kv[5], kv[6], kv[7]);
}

// ---------------- FDU middle: Z = i*c scaling (half in/out, x4) ----------------
__global__ void czi_k(const __half* __restrict__ Xf, const float* __restrict__ delta,
                      __half* __restrict__ Z, const float* __restrict__ sigp) {
    size_t idx = (size_t)blockIdx.x * 256 + threadIdx.x;
    size_t g0 = idx * 4;
    int e = (int)(g0 & (EDsz - 1));
    int k = (int)((g0 >> 11) & (SEGsz - 1));
    int z = (int)(g0 >> 19);
    float sig = sigp[0];
    float f = (float)((k < 128) ? k : k - 256) * (1.0f / 256.0f);
    float gk = __expf(-f * f * sig * sig);
    float w = 6.283185307179586f * f * gk;
    float4 dt = *(const float4*)(delta + ((size_t)z * SEGsz + k) * EDsz + e);
    size_t base = ((size_t)z * 2 * SEGsz + k) * EDsz + e;
    __half2 xr01 = *(const __half2*)(Xf + base);
    __half2 xr23 = *(const __half2*)(Xf + base + 2);
    __half2 xi01 = *(const __half2*)(Xf + base + (size_t)SEGsz * EDsz);
    __half2 xi23 = *(const __half2*)(Xf + base + (size_t)SEGsz * EDsz + 2);
    float c0 = w / (dt.x + 1e-5f), c1 = w / (dt.y + 1e-5f);
    float c2 = w / (dt.z + 1e-5f), c3 = w / (dt.w + 1e-5f);
    float2 fr01 = __half22float2(xr01), fr23 = __half22float2(xr23);
    float2 fi01 = __half22float2(xi01), fi23 = __half22float2(xi23);
    *(uint2*)(Z + base) = pack4h(-c0 * fi01.x, -c1 * fi01.y, -c2 * fi23.x, -c3 * fi23.y);
    *(uint2*)(Z + base + (size_t)SEGsz * EDsz) = pack4h(c0 * fr01.x, c1 * fr01.y, c2 * fr23.x, c3 * fr23.y);
}

// ---------------- segment scan (prefetch + fused next-seg Kerr emit) -----------
__global__ void scan_k(const float* __restrict__ K, const float* __restrict__ delta,
                       const float* __restrict__ xs, const float* __restrict__ Yf,
                       const float* __restrict__ dC, const float* __restrict__ Alog,
                       const float* __restrict__ Dpv, float* __restrict__ y,
                       __half* __restrict__ kehN, int s0, int emit) {
    int b = blockIdx.x >> 4;
    int e = ((blockIdx.x & 15) << 7) + threadIdx.x;
    float A0 = -__expf(Alog[e * 2 + 0]);
    float A1 = -__expf(Alog[e * 2 + 1]);
    float Dpe = Dpv[e];
    float h0 = 0.f, h1 = 0.f;
    size_t rL = (size_t)(b * Lsz + s0);
    size_t rS = (size_t)(b * SEGsz);
    float Kv = K[rS * EDsz + e];
    float dg = delta[rL * EDsz + e];
    float xv = xs[rL * EDsz + e];
    float Yv = Yf[rL * EDsz + e];
    float C0 = __ldg(dC + rL * DCsz + 64);
    float C1 = __ldg(dC + rL * DCsz + 65);
    for (int t = 0; t < SEGsz; t++) {
        float Kn = 0.f, dn = 0.f, xn = 0.f, Yn = 0.f, C0n = 0.f, C1n = 0.f;
        if (t + 1 < SEGsz) {
            Kn  = K[(rS + 1) * EDsz + e];
            dn  = delta[(rL + 1) * EDsz + e];
            xn  = xs[(rL + 1) * EDsz + e];
            Yn  = Yf[(rL + 1) * EDsz + e];
            C0n = __ldg(dC + (rL + 1) * DCsz + 64);
            C1n = __ldg(dC + (rL + 1) * DCsz + 65);
        }
        float Kdy = Kv * Yv;
        {
            float KC = Kv * C0;
            float AmK = A0 * (1.f - KC);
            float Ak  = AmK * (1.f + KC);
            float Bk  = -AmK * Kv;
            float dA  = __expf(dg * Ak);
            h0 = dA * h0 + dg * Bk * xv + Kdy;
        }
        {
            float KC = Kv * C1;
            float AmK = A1 * (1.f - KC);
            float Ak  = AmK * (1.f + KC);
            float Bk  = -AmK * Kv;
            float dA  = __expf(dg * Ak);
            h1 = dA * h1 + dg * Bk * xv + Kdy;
        }
        float yv = h0 * C0 + h1 * C1 + Dpe * xv;
        y[rL * EDsz + e] = yv;
        if (emit) {
            float xgN = xs[(rL + SEGsz) * EDsz + e];
            float d = xgN - yv; d = d * d;
            kehN[rS * EDsz + e] = __float2half_rn(d / (1.f + d));
        }
        rL++; rS++;
        Kv = Kn; dg = dn; xv = xn; Yv = Yn; C0 = C0n; C1 = C1n;
    }
}

// ---------------- gate: yg = y * silu(z) -> fp16 (x4) ----------------
__global__ void gate_k(const float* __restrict__ y, const float* __restrict__ xz,
                       __half* __restrict__ gh) {
    size_t idx = (size_t)blockIdx.x * 256 + threadIdx.x;
    size_t g0 = idx * 4;
    int e = (int)(g0 & (EDsz - 1));
    size_t row = g0 >> 11;
    float4 z = *(const float4*)(xz + row * (2 * EDsz) + EDsz + e);
    float4 yv = *(const float4*)(y + g0);
    float r0 = yv.x * z.x / (1.f + __expf(-z.x));
    float r1 = yv.y * z.y / (1.f + __expf(-z.y));
    float r2 = yv.z * z.z / (1.f + __expf(-z.z));
    float r3 = yv.w * z.w / (1.f + __expf(-z.w));
    *(uint2*)(gh + g0) = pack4h(r0, r1, r2, r3);
}

// ---------------- host ----------------
static float* symAddr(const void* sym) {
    void* p = nullptr;
    cudaGetSymbolAddress(&p, sym);
    return (float*)p;
}
static __half* symAddrH(const void* sym) {
    void* p = nullptr;
    cudaGetSymbolAddress(&p, sym);
    return (__half*)p;
}

extern "C" void kernel_launch(void* const* d_in, const int* in_sizes, int n_in,
                              void* d_out, int out_size) {
    const float* x     = (const float*)d_in[0];
    const float* rms_w = (const float*)d_in[1];
    const float* in_w  = (const float*)d_in[2];
    const float* c1_w  = (const float*)d_in[3];
    const float* c1_b  = (const float*)d_in[4];
    const float* c2_w  = (const float*)d_in[5];
    const float* c2_b  = (const float*)d_in[6];
    const float* xp_w  = (const float*)d_in[7];
    const float* dt_w  = (const float*)d_in[8];
    const float* dt_b  = (const float*)d_in[9];
    const float* A_log = (const float*)d_in[10];
    const float* Dp    = (const float*)d_in[11];
    const float* out_w = (const float*)d_in[12];
    const float* k1_w  = (const float*)d_in[13];
    const float* k1_b  = (const float*)d_in[14];
    const float* k2_w  = (const float*)d_in[15];
    const float* k3_w  = (const float*)d_in[16];
    const float* ln_g  = (const float*)d_in[17];
    const float* ln_b  = (const float*)d_in[18];
    const float* k_al  = (const float*)d_in[19];
    const float* sigma = (const float*)d_in[20];

    float* xz    = symAddr(g_xz);
    float* xs    = symAddr(g_xs);
    float* delta = symAddr(g_delta);
    float* dC    = symAddr(g_dC);
    float* y     = symAddr(g_y);
    float* K     = symAddr(g_K);
    float* h3    = symAddr(g_h3);
    float* Yf    = symAddr(g_Yf);
    __half *xnh  = symAddrH(g_xnh);
    __half *inwh = symAddrH(g_inwh);
    __half *xsh  = symAddrH(g_xsh);
    __half *xpwh = symAddrH(g_xpwh);
    __half *keh  = symAddrH(g_keh);
    __half *k1wh = symAddrH(g_k1wh);
    __half *h1h  = symAddrH(g_h1h);
    __half *k2wh = symAddrH(g_k2wh);
    __half *h2h  = symAddrH(g_h2h);
    __half *k3wh = symAddrH(g_k3wh);
    __half *ygh  = symAddrH(g_ygh);
    __half *owh  = symAddrH(g_owh);
    __half *dft1h= symAddrH(g_dft1h);
    __half *dft2h= symAddrH(g_dft2h);
    __half *Xfh  = symAddrH(g_Xfh);
    __half *Zbh  = symAddrH(g_Zbh);
    float* h = (float*)d_out;

    const int MROWS = Bsz * Lsz;              // 8192
    const int SROWS = Bsz * SEGsz;            // 1024
    const int NB = Bsz * NSEG;                // 32 FDU batches

    dft_init_k<<<256, 256>>>();
    cudaMemcpyAsync(h, x, sizeof(float) * (size_t)MROWS * DMsz, cudaMemcpyDeviceToDevice);

    for (int i = 0; i < NLsz; i++) {
        const float* rms = rms_w + (size_t)i * DMsz;
        const float* inw = in_w  + (size_t)i * 2 * EDsz * DMsz;
        const float* w1c = c1_w + (size_t)i * EDsz * 2;
        const float* b1c = c1_b + (size_t)i * EDsz;
        const float* w2c = c2_w + (size_t)i * EDsz * 2;
        const float* b2c = c2_b + (size_t)i * EDsz;
        const float* xpw = xp_w + (size_t)i * DCsz * EDsz;
        const float* dtw = dt_w + (size_t)i * EDsz * DTRsz;
        const float* dtb = dt_b + (size_t)i * EDsz;
        const float* alg = A_log + (size_t)i * EDsz * 2;
        const float* dpp = Dp + (size_t)i * EDsz;
        const float* ow  = out_w + (size_t)i * DMsz * EDsz;
        const float* k1w = k1_w + (size_t)i * 3 * EDsz * EDsz;
        const float* k1b = k1_b + (size_t)i * 3 * EDsz;
        const float* k2w = k2_w + (size_t)i * EDsz * 3 * EDsz;
        const float* k3w = k3_w + (size_t)i * EDsz * EDsz;
        const float* lng = ln_g + (size_t)i * EDsz;
        const float* lnb = ln_b + (size_t)i * EDsz;
        const float* kal = k_al + (size_t)i * EDsz;
        const float* sig = sigma + i;

        wconv_k<<<(2*EDsz*DMsz/8 + 255)/256, 256>>>(inw, inwh, 2*EDsz*DMsz/8);
        wconv_k<<<(3*EDsz*EDsz/8 + 255)/256, 256>>>(k1w, k1wh, 3*EDsz*EDsz/8);
        wconv_k<<<(3*EDsz*EDsz/8 + 255)/256, 256>>>(k2w, k2wh, 3*EDsz*EDsz/8);
        wconv_k<<<(EDsz*EDsz/8 + 255)/256, 256>>>(k3w, k3wh, EDsz*EDsz/8);
        wconv_k<<<(DMsz*EDsz/8 + 255)/256, 256>>>(ow, owh, DMsz*EDsz/8);
        xppad_k<<<(128*EDsz/8)/256, 256>>>(xpw, xpwh);

        rmsnorm_k<<<MROWS, 256>>>(h, rms, xnh);

        // xz = xn @ in_w^T   (8192 x 4096, K=1024)
        ts_gemm_k<0,false><<<dim3(32, 64), 256>>>(
            xnh, inwh, xz, nullptr, DMsz, DMsz, 2*EDsz, 2*EDsz, DMsz, nullptr);

        conv_silu_k<<<(MROWS * EDsz / 4) / 256, 256>>>(xz, w1c, b1c, w2c, b2c, xs, xsh);

        // dC = xs @ xp_w^T   (8192 x 66, K=2048)
        ts_gemm_k<0,false><<<dim3(1, 64), 256>>>(
            xsh, xpwh, dC, nullptr, EDsz, EDsz, DCsz, DCsz, EDsz, nullptr);

        // delta = softplus(dr @ dt_w^T + dt_b)
        gemm_sp_k<<<dim3(16, 64), 256>>>(dC, DCsz, dtw, DTRsz,
                                         delta, EDsz, EDsz, DTRsz, dtb);

        // ----- batched FDU over all 8 segments (all-half) -----
        // stage 1: [Xr; Xi] = dft1 @ xs_seg   (512 x 2048, K=256, batch=32) -> half
        tgemm_nnh_k<true><<<dim3(16, 4, NB), 256>>>(
            dft1h, SEGsz, xsh, EDsz, (long long)SEGsz * EDsz,
            nullptr, Xfh, EDsz, (long long)2 * SEGsz * EDsz, SEGsz);
        czi_k<<<((size_t)NB * SEGsz * EDsz / 4) / 256, 256>>>(Xfh, delta, Zbh, sig);
        // stage 2: Yf = dft2 @ [Zr; Zi]       (256 x 2048, K=512, batch=32) -> fp32
        tgemm_nnh_k<false><<<dim3(16, 2, NB), 256>>>(
            dft2h, 2 * SEGsz, Zbh, EDsz, (long long)2 * SEGsz * EDsz,
            Yf, nullptr, EDsz, (long long)SEGsz * EDsz, 2 * SEGsz);

        // Kerr for s=0 (yh = 0)
        kerr_k<<<(SROWS * EDsz / 4) / 256, 256>>>(xs, keh, 0);

        for (int s = 0; s < NSEG; s++) {
            int s0 = s * SEGsz;

            // kproj1: h1 = relu(Kerr @ k1_w^T + b)  (1024 x 6144, K=2048) -> fp16
            ts_gemm_k<1,true><<<dim3(48, 8), 256>>>(
                keh, k1wh, nullptr, h1h, EDsz, EDsz, 3*EDsz, 3*EDsz, EDsz, k1b);
            // kproj2: h2 = relu(h1 @ k2_w^T)        (1024 x 2048, K=6144) -> fp16
            ts_gemm_k<2,true><<<dim3(16, 8), 256>>>(
                h1h, k2wh, nullptr, h2h, 3*EDsz, 3*EDsz, EDsz, EDsz, 3*EDsz, nullptr);
            // kproj3: h3 = h2 @ k3_w^T              (1024 x 2048, K=2048) -> fp32
            ts_gemm_k<0,false><<<dim3(16, 8), 256>>>(
                h2h, k3wh, h3, nullptr, EDsz, EDsz, EDsz, EDsz, EDsz, nullptr);

            kup_k<<<SROWS, 256>>>(h3, lng, lnb, kal, K, s == 0 ? 1 : 0);

            // scan emits y for this segment AND Kerr for the next one
            scan_k<<<Bsz * (EDsz / 128), 128>>>(K, delta, xs, Yf, dC, alg, dpp, y,
                                                keh, s0, (s + 1 < NSEG) ? 1 : 0);
        }

        gate_k<<<(MROWS * EDsz / 4) / 256, 256>>>(y, xz, ygh);

        // h += yg @ out_w^T   (8192 x 1024, K=2048)  [accumulate]
        ts_gemm_k<4,false><<<dim3(8, 64), 256>>>(
            ygh, owh, h, nullptr, EDsz, EDsz, DMsz, DMsz, EDsz, nullptr);
    }
}

// round 16
// speedup vs baseline: 1.0979x; 1.0979x over previous
#include <cuda_runtime.h>
#include <cuda_fp16.h>
#include <math.h>
#include <stdint.h>

// ---------------- problem constants ----------------
#define Bsz   4
#define Lsz   2048
#define DMsz  1024
#define EDsz  2048
#define SEGsz 256
#define NSEG  8
#define NLsz  2
#define DTRsz 64
#define DCsz  66   // DTR + N

// ---------------- fp32 scratch ----------------
__device__ float g_xz   [(size_t)Bsz*Lsz*2*EDsz];
__device__ float g_xs   [(size_t)Bsz*Lsz*EDsz];
__device__ float g_delta[(size_t)Bsz*Lsz*EDsz];
__device__ float g_dC   [(size_t)Bsz*Lsz*DCsz];
__device__ float g_y    [(size_t)Bsz*Lsz*EDsz];
__device__ float g_K    [(size_t)Bsz*SEGsz*EDsz];
__device__ float g_h3   [(size_t)Bsz*SEGsz*EDsz];
__device__ float g_Xf   [(size_t)Bsz*NSEG*2*SEGsz*EDsz];
__device__ float g_Zb   [(size_t)Bsz*NSEG*2*SEGsz*EDsz];
__device__ float g_Yf   [(size_t)Bsz*Lsz*EDsz];
__device__ float g_dft1 [2*SEGsz*SEGsz];
__device__ float g_dft2 [SEGsz*2*SEGsz];

// ---------------- fp16 operands ----------------
__device__ __half g_xnh [(size_t)Bsz*Lsz*DMsz];
__device__ __half g_inwh[(size_t)2*EDsz*DMsz];
__device__ __half g_xsh [(size_t)Bsz*Lsz*EDsz];
__device__ __half g_xpwh[(size_t)128*EDsz];
__device__ __half g_keh [(size_t)Bsz*SEGsz*EDsz];
__device__ __half g_k1wh[(size_t)3*EDsz*EDsz];
__device__ __half g_h1h [(size_t)Bsz*SEGsz*3*EDsz];
__device__ __half g_k2wh[(size_t)EDsz*3*EDsz];
__device__ __half g_h2h [(size_t)Bsz*SEGsz*EDsz];
__device__ __half g_k3wh[(size_t)EDsz*EDsz];
__device__ __half g_ygh [(size_t)Bsz*Lsz*EDsz];
__device__ __half g_owh [(size_t)DMsz*EDsz];

// ---------------- small helpers ----------------
__device__ __forceinline__ uint2 pack4h(float a, float b, float c, float d) {
    __half2 h0 = __floats2half2_rn(a, b), h1 = __floats2half2_rn(c, d);
    uint2 u; u.x = *(uint32_t*)&h0; u.y = *(uint32_t*)&h1; return u;
}
__device__ __forceinline__ uint4 pack8h(float4 a, float4 b) {
    __half2 h0 = __floats2half2_rn(a.x, a.y), h1 = __floats2half2_rn(a.z, a.w);
    __half2 h2 = __floats2half2_rn(b.x, b.y), h3 = __floats2half2_rn(b.z, b.w);
    uint4 u; u.x = *(uint32_t*)&h0; u.y = *(uint32_t*)&h1;
    u.z = *(uint32_t*)&h2; u.w = *(uint32_t*)&h3; return u;
}
__device__ __forceinline__ float blkSum(float v) {
    __shared__ float sh[32];
    __syncthreads();
    int lane = threadIdx.x & 31, w = threadIdx.x >> 5;
#pragma unroll
    for (int o = 16; o; o >>= 1) v += __shfl_down_sync(0xffffffffu, v, o);
    if (!lane) sh[w] = v;
    __syncthreads();
    if (w == 0) {
        v = (lane < (int)(blockDim.x >> 5)) ? sh[lane] : 0.f;
#pragma unroll
        for (int o = 16; o; o >>= 1) v += __shfl_down_sync(0xffffffffu, v, o);
        if (!lane) sh[0] = v;
    }
    __syncthreads();
    return sh[0];
}

// ---------------- mma / async primitives ----------------
__device__ __forceinline__ void mma16816(float* d, const uint32_t* a, uint32_t b0, uint32_t b1) {
    asm volatile(
        "mma.sync.aligned.m16n8k16.row.col.f32.f16.f16.f32 "
        "{%0,%1,%2,%3}, {%4,%5,%6,%7}, {%8,%9}, {%0,%1,%2,%3};\n"
        : "+f"(d[0]), "+f"(d[1]), "+f"(d[2]), "+f"(d[3])
        : "r"(a[0]), "r"(a[1]), "r"(a[2]), "r"(a[3]), "r"(b0), "r"(b1));
}
__device__ __forceinline__ void ldsm4(uint32_t* r, uint32_t addr) {
    asm volatile("ldmatrix.sync.aligned.m8n8.x4.shared.b16 {%0,%1,%2,%3}, [%4];\n"
        : "=r"(r[0]), "=r"(r[1]), "=r"(r[2]), "=r"(r[3]) : "r"(addr));
}
__device__ __forceinline__ void cpa16(uint32_t dst, const void* src) {
    asm volatile("cp.async.cg.shared.global [%0], [%1], 16;\n" :: "r"(dst), "l"(src));
}
__device__ __forceinline__ void cpa_commit() { asm volatile("cp.async.commit_group;\n" ::: "memory"); }
template<int N> __device__ __forceinline__ void cpa_wait() {
    asm volatile("cp.async.wait_group %0;\n" :: "n"(N) : "memory");
}

// ================= single-fp16 mma.sync NT GEMM =================
// D = A(MxK) @ B(NxK)^T, fp16 inputs, fp32 accum.
// EPI: 0 none, 1 bias+relu, 2 relu, 4 C += result.  PAIR: emit fp16 output.
#define TS_STAGE 16384
template<int EPI, bool PAIR>
__global__ __launch_bounds__(256, 2) void ts_gemm_k(
    const __half* __restrict__ Ahg, const __half* __restrict__ Bhg,
    float* __restrict__ C, __half* __restrict__ Oh,
    int lda, int ldb, int ldc, int Nn, int K, const float* __restrict__ bias)
{
    __shared__ __align__(16) char sm[2 * TS_STAGE];
    const int tid = threadIdx.x;
    const int lane = tid & 31, wid = tid >> 5;
    const int wm = wid & 1, wn = wid >> 1;
    const int m0 = blockIdx.y * 128, n0 = blockIdx.x * 128;

    float acc[4][4][4];
#pragma unroll
    for (int i = 0; i < 4; i++)
#pragma unroll
        for (int j = 0; j < 4; j++)
#pragma unroll
            for (int q = 0; q < 4; q++) acc[i][j][q] = 0.f;

    const uint32_t smBase = (uint32_t)__cvta_generic_to_shared(sm);
    const int frow0 = tid >> 2;
    const int fc    = tid & 3;
    auto fill = [&](int k0, int st) {
        const uint32_t base = smBase + st * TS_STAGE;
#pragma unroll
        for (int i = 0; i < 2; i++) {
            int row = frow0 + i * 64;
            uint32_t off = (uint32_t)(row * 64 + fc * 16);
            uint32_t dsw = off ^ ((off >> 3) & 0x30);
            cpa16(base +        dsw, Ahg + (size_t)(m0 + row) * lda + k0 + fc * 8);
            cpa16(base + 8192 + dsw, Bhg + (size_t)(n0 + row) * ldb + k0 + fc * 8);
        }
        cpa_commit();
    };

    const int aRow = wm * 64 + (lane & 15);
    const int aCh  = (lane >> 4);
    const int bRow = wn * 32 + (lane & 7) + ((lane & 16) >> 1);
    const int bCh  = ((lane & 8) >> 3);

    const int kt = K >> 5;
    fill(0, 0);
    for (int t = 0; t < kt; t++) {
        if (t + 1 < kt) { fill((t + 1) << 5, (t + 1) & 1); cpa_wait<1>(); }
        else            { cpa_wait<0>(); }
        __syncthreads();
        const uint32_t base = smBase + (t & 1) * TS_STAGE;
#pragma unroll
        for (int ks = 0; ks < 2; ks++) {
            uint32_t bh[2][4];
#pragma unroll
            for (int nt2 = 0; nt2 < 2; nt2++) {
                uint32_t off = (uint32_t)((bRow + nt2 * 16) * 64 + (bCh + ks * 2) * 16);
                uint32_t dsw = off ^ ((off >> 3) & 0x30);
                ldsm4(bh[nt2], base + 8192 + dsw);
            }
#pragma unroll
            for (int mt = 0; mt < 4; mt++) {
                uint32_t off = (uint32_t)((aRow + mt * 16) * 64 + (aCh + ks * 2) * 16);
                uint32_t dsw = off ^ ((off >> 3) & 0x30);
                uint32_t ah[4];
                ldsm4(ah, base + dsw);
#pragma unroll
                for (int n8 = 0; n8 < 4; n8++)
                    mma16816(acc[mt][n8], ah, bh[n8 >> 1][(n8 & 1) * 2], bh[n8 >> 1][(n8 & 1) * 2 + 1]);
            }
        }
        __syncthreads();
    }

    const int g = lane >> 2, cc = (lane & 3) * 2;
#pragma unroll
    for (int mt = 0; mt < 4; mt++) {
        long long m = m0 + wm * 64 + mt * 16 + g;
#pragma unroll
        for (int n8 = 0; n8 < 4; n8++) {
            int col = n0 + wn * 32 + n8 * 8 + cc;
            if (col >= Nn) continue;
            float* a4 = acc[mt][n8];
            float2 v0 = make_float2(a4[0], a4[1]);
            float2 v1 = make_float2(a4[2], a4[3]);
            if (EPI == 1) {
                float b0 = bias[col], b1 = bias[col + 1];
                v0.x = fmaxf(v0.x + b0, 0.f); v0.y = fmaxf(v0.y + b1, 0.f);
                v1.x = fmaxf(v1.x + b0, 0.f); v1.y = fmaxf(v1.y + b1, 0.f);
            } else if (EPI == 2) {
                v0.x = fmaxf(v0.x, 0.f); v0.y = fmaxf(v0.y, 0.f);
                v1.x = fmaxf(v1.x, 0.f); v1.y = fmaxf(v1.y, 0.f);
            }
            if (PAIR) {
                *(__half2*)(Oh + m * ldc + col)       = __floats2half2_rn(v0.x, v0.y);
                *(__half2*)(Oh + (m + 8) * ldc + col) = __floats2half2_rn(v1.x, v1.y);
            } else {
                float* p0 = C + m * ldc + col;
                float* p1 = C + (m + 8) * ldc + col;
                if (EPI == 4) {
                    float2 o0 = *(float2*)p0, o1 = *(float2*)p1;
                    v0.x += o0.x; v0.y += o0.y; v1.x += o1.x; v1.y += o1.y;
                }
                *(float2*)p0 = v0;
                *(float2*)p1 = v1;
            }
        }
    }
}

// ---------------- DFT table init ----------------
__global__ void dft_init_k() {
    int idx = blockIdx.x * 256 + threadIdx.x;
    int t = idx & 255, k = idx >> 8;
    int p = (k * t) & 255;
    float ang = 6.283185307179586f * (float)p * (1.0f / 256.0f);
    float s, c;
    sincosf(ang, &s, &c);
    g_dft1[k * 256 + t]         = c;
    g_dft1[(k + 256) * 256 + t] = -s;
    g_dft2[t * 512 + k]         = c  * (1.0f / 256.0f);
    g_dft2[t * 512 + 256 + k]   = -s * (1.0f / 256.0f);
}

// ---------------- weight convert (fp32 -> fp16), 8 elems/thread ----------------
__global__ void wconv_k(const float* __restrict__ src, __half* __restrict__ dh, int n8) {
    int i = blockIdx.x * 256 + threadIdx.x;
    if (i >= n8) return;
    const float4* s = (const float4*)src + (size_t)i * 2;
    float4 a = s[0], b = s[1];
    *((uint4*)dh + i) = pack8h(a, b);
}
// xp_w padded to 128 rows (rows 66..127 zero), 8 elems/thread
__global__ void xppad_k(const float* __restrict__ src, __half* __restrict__ dh) {
    int i = blockIdx.x * 256 + threadIdx.x;   // 32768 threads
    int g0 = i * 8;
    int row = g0 >> 11, col = g0 & (EDsz - 1);
    float4 a = make_float4(0, 0, 0, 0), b = a;
    if (row < DCsz) {
        a = *(const float4*)(src + (size_t)row * EDsz + col);
        b = *(const float4*)(src + (size_t)row * EDsz + col + 4);
    }
    *((uint4*)dh + i) = pack8h(a, b);
}

// ---------------- RMSNorm -> fp16 (vectorized) ----------------
__global__ void rmsnorm_k(const float* __restrict__ h, const float* __restrict__ w,
                          __half* __restrict__ oh) {
    size_t base = (size_t)blockIdx.x * DMsz;
    int tid = threadIdx.x;                        // 256 threads x 4 = 1024
    float4 v = *((const float4*)(h + base) + tid);
    float s = v.x * v.x + v.y * v.y + v.z * v.z + v.w * v.w;
    s = blkSum(s);
    float r = rsqrtf(s * (1.0f / DMsz) + 1e-5f);
    float4 w4 = *((const float4*)w + tid);
    *((uint2*)(oh + base) + tid) = pack4h(v.x * r * w4.x, v.y * r * w4.y,
                                          v.z * r * w4.z, v.w * r * w4.w);
}

// ---------------- fused double depthwise conv (k=2) + SiLU (x4) ----------------
__global__ void conv_silu_k(const float* __restrict__ xz,
                            const float* __restrict__ c1w, const float* __restrict__ c1b,
                            const float* __restrict__ c2w, const float* __restrict__ c2b,
                            float* __restrict__ xs, __half* __restrict__ xsh) {
    size_t idx = (size_t)blockIdx.x * 256 + threadIdx.x;    // over B*L*ED/4
    size_t g0 = idx * 4;
    int e = (int)(g0 & (EDsz - 1));
    int l = (int)((g0 >> 11) & (Lsz - 1));
    int b = (int)(g0 >> 22);
    const float* base = xz + (size_t)(b * Lsz) * (2 * EDsz) + e;
    float4 x2 = *(const float4*)(base + (size_t)l * (2 * EDsz));
    float4 x1 = (l >= 1) ? *(const float4*)(base + (size_t)(l - 1) * (2 * EDsz)) : make_float4(0,0,0,0);
    float4 x0 = (l >= 2) ? *(const float4*)(base + (size_t)(l - 2) * (2 * EDsz)) : make_float4(0,0,0,0);
    float4 w1a = *(const float4*)(c1w + e * 2);
    float4 w1b = *(const float4*)(c1w + e * 2 + 4);
    float4 w2a = *(const float4*)(c2w + e * 2);
    float4 w2b = *(const float4*)(c2w + e * 2 + 4);
    float4 b1 = *(const float4*)(c1b + e);
    float4 b2 = *(const float4*)(c2b + e);
    float r[4];
    {
        float X0[4] = {x0.x, x0.y, x0.z, x0.w};
        float X1[4] = {x1.x, x1.y, x1.z, x1.w};
        float X2[4] = {x2.x, x2.y, x2.z, x2.w};
        float W10[4] = {w1a.x, w1a.z, w1b.x, w1b.z};
        float W11[4] = {w1a.y, w1a.w, w1b.y, w1b.w};
        float W20[4] = {w2a.x, w2a.z, w2b.x, w2b.z};
        float W21[4] = {w2a.y, w2a.w, w2b.y, w2b.w};
        float B1[4] = {b1.x, b1.y, b1.z, b1.w};
        float B2[4] = {b2.x, b2.y, b2.z, b2.w};
#pragma unroll
        for (int j = 0; j < 4; j++) {
            float y1a = (l >= 1) ? (B1[j] + X0[j] * W10[j] + X1[j] * W11[j]) : 0.f;
            float y1b = B1[j] + X1[j] * W10[j] + X2[j] * W11[j];
            float y2 = B2[j] + y1a * W20[j] + y1b * W21[j];
            r[j] = y2 / (1.f + __expf(-y2));
        }
    }
    *(float4*)(xs + g0) = make_float4(r[0], r[1], r[2], r[3]);
    *(uint2*)(xsh + g0) = pack4h(r[0], r[1], r[2], r[3]);
}

// ---------------- fp16 NN GEMM (FDU, batched): C = A(MxK) @ B(KxN) -------------
__global__ __launch_bounds__(256) void tgemm_nn_k(
    const float* __restrict__ A, int lda, long long sA,
    const float* __restrict__ Bm, int ldb, long long sB,
    float* __restrict__ C, int ldc, long long sC,
    int K)
{
    __shared__ __align__(16) __half Ah[128][40];
    __shared__ __align__(16) __half Bh[128][40];

    const int bz = blockIdx.z;
    A  += (long long)bz * sA;
    Bm += (long long)bz * sB;
    C  += (long long)bz * sC;
    const int m0 = blockIdx.y * 128, n0 = blockIdx.x * 128;
    const int tid = threadIdx.x;
    const int lane = tid & 31, wid = tid >> 5;
    const int wm = wid & 1, wn = wid >> 1;

    float acc[4][4][4];
#pragma unroll
    for (int i = 0; i < 4; i++)
#pragma unroll
        for (int j = 0; j < 4; j++)
#pragma unroll
            for (int q = 0; q < 4; q++) acc[i][j][q] = 0.f;

    const int ak4 = tid & 7;
    const int ar0 = tid >> 3;
    const int bn4 = tid & 31;
    const int bk0 = tid >> 5;

    float4 av[4], bv[4];
    auto loadTile = [&](int k0) {
        const float* pa = A + (long long)(m0 + ar0) * lda + k0 + ak4 * 4;
#pragma unroll
        for (int i = 0; i < 4; i++) av[i] = *(const float4*)(pa + (long long)(32 * i) * lda);
        const float* pb = Bm + (long long)(k0 + bk0) * ldb + n0 + bn4 * 4;
#pragma unroll
        for (int i = 0; i < 4; i++) bv[i] = *(const float4*)(pb + (long long)(8 * i) * ldb);
    };
    auto storeTile = [&]() {
#pragma unroll
        for (int i = 0; i < 4; i++) {
            int row = ar0 + 32 * i;
            float4 v = av[i];
            __half2* dh = (__half2*)&Ah[row][ak4 * 4];
            dh[0] = __floats2half2_rn(v.x, v.y);
            dh[1] = __floats2half2_rn(v.z, v.w);
        }
#pragma unroll
        for (int i = 0; i < 4; i++) {
            int kr = bk0 + 8 * i;
            float4 v = bv[i];
            float s4[4] = {v.x, v.y, v.z, v.w};
#pragma unroll
            for (int j = 0; j < 4; j++)
                Bh[bn4 * 4 + j][kr] = __float2half_rn(s4[j]);
        }
    };

    const uint32_t aBase = (uint32_t)__cvta_generic_to_shared(&Ah[0][0]);
    const uint32_t bBase = (uint32_t)__cvta_generic_to_shared(&Bh[0][0]);
    const uint32_t aOff = ((wm * 64 + (lane & 15)) * 40 + ((lane >> 4) << 3)) * 2;
    const uint32_t bOff = ((wn * 32 + (lane & 7) + ((lane & 16) >> 1)) * 40 + (lane & 8)) * 2;

    const int kt = K >> 5;
    loadTile(0);
    for (int t = 0; t < kt; t++) {
        storeTile();
        __syncthreads();
        if (t + 1 < kt) loadTile((t + 1) << 5);
#pragma unroll
        for (int ks = 0; ks < 2; ks++) {
            uint32_t bhf[2][4];
#pragma unroll
            for (int nt2 = 0; nt2 < 2; nt2++)
                ldsm4(bhf[nt2], bBase + bOff + nt2 * 16 * 80 + ks * 32);
#pragma unroll
            for (int mt = 0; mt < 4; mt++) {
                uint32_t ahf[4];
                ldsm4(ahf, aBase + aOff + mt * 16 * 80 + ks * 32);
#pragma unroll
                for (int n8 = 0; n8 < 4; n8++)
                    mma16816(acc[mt][n8], ahf, bhf[n8 >> 1][(n8 & 1) * 2], bhf[n8 >> 1][(n8 & 1) * 2 + 1]);
            }
        }
        __syncthreads();
    }

    const int g = lane >> 2, cc = (lane & 3) * 2;
#pragma unroll
    for (int mt = 0; mt < 4; mt++) {
        long long m = m0 + wm * 64 + mt * 16 + g;
#pragma unroll
        for (int n8 = 0; n8 < 4; n8++) {
            int col = n0 + wn * 32 + n8 * 8 + cc;
            float* a4 = acc[mt][n8];
            *(float2*)(C + m * ldc + col)       = make_float2(a4[0], a4[1]);
            *(float2*)(C + (m + 8) * ldc + col) = make_float2(a4[2], a4[3]);
        }
    }
}

// ---------------- SIMT fp32 GEMM (delta only: bias+softplus) ----------------
__global__ __launch_bounds__(256) void gemm_sp_k(
    const float* __restrict__ A, int lda,
    const float* __restrict__ Bm, int ldb,
    float* __restrict__ C, int ldc,
    int N, int K, const float* __restrict__ bias)
{
    __shared__ float As[16][128];
    __shared__ float Bs[16][132];
    const int m0 = blockIdx.y * 128, n0 = blockIdx.x * 128;
    const int tid = threadIdx.x;
    const int tx = tid & 15, ty = tid >> 4;
    float acc[8][8];
#pragma unroll
    for (int i = 0; i < 8; i++)
#pragma unroll
        for (int j = 0; j < 8; j++) acc[i][j] = 0.f;
    const bool a4 = ((lda & 3) == 0);

    for (int k0 = 0; k0 < K; k0 += 16) {
        {
            int r = tid >> 2, c4 = (tid & 3) << 2;
#pragma unroll
            for (int rr = 0; rr < 2; rr++) {
                int row = r + rr * 64;
                const float* p = A + (long long)(m0 + row) * lda + (k0 + c4);
                float4 v;
                if (a4) v = *(const float4*)p;
                else { v.x = p[0]; v.y = p[1]; v.z = p[2]; v.w = p[3]; }
                As[c4 + 0][row] = v.x; As[c4 + 1][row] = v.y;
                As[c4 + 2][row] = v.z; As[c4 + 3][row] = v.w;
            }
        }
        {
            int r = tid >> 2, c4 = (tid & 3) << 2;
#pragma unroll
            for (int rr = 0; rr < 2; rr++) {
                int row = r + rr * 64;
                float4 v = make_float4(0.f, 0.f, 0.f, 0.f);
                if (n0 + row < N) {
                    const float* p = Bm + (long long)(n0 + row) * ldb + (k0 + c4);
                    v.x = p[0]; v.y = p[1]; v.z = p[2]; v.w = p[3];
                }
                Bs[c4 + 0][row] = v.x; Bs[c4 + 1][row] = v.y;
                Bs[c4 + 2][row] = v.z; Bs[c4 + 3][row] = v.w;
            }
        }
        __syncthreads();
#pragma unroll
        for (int kk = 0; kk < 16; kk++) {
            float a[8], b[8];
            *(float4*)&a[0] = *(const float4*)&As[kk][ty * 8];
            *(float4*)&a[4] = *(const float4*)&As[kk][ty * 8 + 4];
            *(float4*)&b[0] = *(const float4*)&Bs[kk][tx * 8];
            *(float4*)&b[4] = *(const float4*)&Bs[kk][tx * 8 + 4];
#pragma unroll
            for (int i = 0; i < 8; i++)
#pragma unroll
                for (int j = 0; j < 8; j++)
                    acc[i][j] = fmaf(a[i], b[j], acc[i][j]);
        }
        __syncthreads();
    }
#pragma unroll
    for (int ii = 0; ii < 8; ii++) {
        long long m = m0 + ty * 8 + ii;
        float* Crow = C + m * (long long)ldc;
#pragma unroll
        for (int jj = 0; jj < 8; jj++) {
            int n = n0 + tx * 8 + jj;
            if (n >= N) continue;
            float v = acc[ii][jj] + bias[n];
            Crow[n] = (v > 20.f) ? v : log1pf(expf(v));
        }
    }
}

// ---------------- zero fill (x4) ----------------
__global__ void zero_k(float* p, int n4) {
    int i = blockIdx.x * 256 + threadIdx.x;
    if (i < n4) ((float4*)p)[i] = make_float4(0, 0, 0, 0);
}

// ---------------- Kerr = softsign((xg - yh)^2) -> fp16 (x4) ----------------
__global__ void kerr_k(const float* __restrict__ xs, const float* __restrict__ y,
                       __half* __restrict__ kh, int s0, int first) {
    size_t idx = (size_t)blockIdx.x * 256 + threadIdx.x;   // B*SEG*ED/4
    size_t g0 = idx * 4;
    int e = (int)(g0 & (EDsz - 1));
    int t = (int)((g0 >> 11) & (SEGsz - 1));
    int b = (int)(g0 >> 19);
    float4 xg = *(const float4*)(xs + ((size_t)(b * Lsz + s0 + t)) * EDsz + e);
    float4 yh = make_float4(0, 0, 0, 0);
    if (!first) yh = *(const float4*)(y + ((size_t)(b * Lsz + s0 - SEGsz + t)) * EDsz + e);
    float r[4];
    float dx[4] = {xg.x - yh.x, xg.y - yh.y, xg.z - yh.z, xg.w - yh.w};
#pragma unroll
    for (int j = 0; j < 4; j++) { float d = dx[j] * dx[j]; r[j] = d / (1.f + d); }
    *(uint2*)(kh + g0) = pack4h(r[0], r[1], r[2], r[3]);
}

// ---------------- LayerNorm(h3) -> Knew; K = (1-a)K + a*Knew (x8) ----------------
__global__ void kup_k(const float* __restrict__ h3,
                      const float* __restrict__ lng, const float* __restrict__ lnb,
                      const float* __restrict__ kal, float* __restrict__ K) {
    size_t base = (size_t)blockIdx.x * EDsz;
    int e0 = threadIdx.x * 8;
    float4 va = *(const float4*)(h3 + base + e0);
    float4 vb = *(const float4*)(h3 + base + e0 + 4);
    float v[8] = {va.x, va.y, va.z, va.w, vb.x, vb.y, vb.z, vb.w};
    float s = 0.f;
#pragma unroll
    for (int j = 0; j < 8; j++) s += v[j];
    s = blkSum(s);
    float mu = s * (1.0f / EDsz);
    float q = 0.f;
#pragma unroll
    for (int j = 0; j < 8; j++) { float d = v[j] - mu; q += d * d; }
    q = blkSum(q);
    float rstd = rsqrtf(q * (1.0f / EDsz) + 1e-5f);
    float4 ga = *(const float4*)(lng + e0), gb = *(const float4*)(lng + e0 + 4);
    float4 ba = *(const float4*)(lnb + e0), bb = *(const float4*)(lnb + e0 + 4);
    float4 aa = *(const float4*)(kal + e0), ab = *(const float4*)(kal + e0 + 4);
    float4 ka = *(const float4*)(K + base + e0), kb = *(const float4*)(K + base + e0 + 4);
    float gv[8] = {ga.x, ga.y, ga.z, ga.w, gb.x, gb.y, gb.z, gb.w};
    float bv[8] = {ba.x, ba.y, ba.z, ba.w, bb.x, bb.y, bb.z, bb.w};
    float av2[8] = {aa.x, aa.y, aa.z, aa.w, ab.x, ab.y, ab.z, ab.w};
    float kv[8] = {ka.x, ka.y, ka.z, ka.w, kb.x, kb.y, kb.z, kb.w};
#pragma unroll
    for (int j = 0; j < 8; j++) {
        float kn = gv[j] * (v[j] - mu) * rstd + bv[j];
        float a = fminf(fmaxf(av2[j], 0.01f), 0.99f);
        kv[j] = (1.f - a) * kv[j] + a * kn;
    }
    *(float4*)(K + base + e0)     = make_float4(kv[0], kv[1], kv[2], kv[3]);
    *(float4*)(K + base + e0 + 4) = make_float4(kv[4], kv[5], kv[6], kv[7]);
}

// ---------------- FDU middle: Z = i*c scaling (batched over B*NSEG, x4) ---------
__global__ void czi_k(const float* __restrict__ Xf, const float* __restrict__ delta,
                      float* __restrict__ Z, const float* __restrict__ sigp) {
    size_t idx = (size_t)blockIdx.x * 256 + threadIdx.x;   // B*NSEG*SEG*ED/4
    size_t g0 = idx * 4;
    int e = (int)(g0 & (EDsz - 1));
    int k = (int)((g0 >> 11) & (SEGsz - 1));
    int z = (int)(g0 >> 19);
    float sig = sigp[0];
    float f = (float)((k < 128) ? k : k - 256) * (1.0f / 256.0f);
    float gk = __expf(-f * f * sig * sig);
    float w = 6.283185307179586f * f * gk;
    float4 dt = *(const float4*)(delta + ((size_t)z * SEGsz + k) * EDsz + e);
    size_t base = ((size_t)z * 2 * SEGsz + k) * EDsz + e;
    float4 xr = *(const float4*)(Xf + base);
    float4 xi = *(const float4*)(Xf + base + (size_t)SEGsz * EDsz);
    float c0 = w / (dt.x + 1e-5f), c1 = w / (dt.y + 1e-5f);
    float c2 = w / (dt.z + 1e-5f), c3 = w / (dt.w + 1e-5f);
    *(float4*)(Z + base) = make_float4(-c0 * xi.x, -c1 * xi.y, -c2 * xi.z, -c3 * xi.w);
    *(float4*)(Z + base + (size_t)SEGsz * EDsz) = make_float4(c0 * xr.x, c1 * xr.y, c2 * xr.z, c3 * xr.w);
}

// ---------------- segment scan (software prefetch, 64-thread blocks) ------------
__global__ void scan_k(const float* __restrict__ K, const float* __restrict__ delta,
                       const float* __restrict__ xs, const float* __restrict__ Yf,
                       const float* __restrict__ dC, const float* __restrict__ Alog,
                       const float* __restrict__ Dpv, float* __restrict__ y, int s0) {
    int b = blockIdx.x >> 5;                       // ED/64 = 32 chunks per b
    int e = ((blockIdx.x & 31) << 6) + threadIdx.x;
    float A0 = -__expf(Alog[e * 2 + 0]);
    float A1 = -__expf(Alog[e * 2 + 1]);
    float Dpe = Dpv[e];
    float h0 = 0.f, h1 = 0.f;
    size_t rL = (size_t)(b * Lsz + s0);
    size_t rS = (size_t)(b * SEGsz);
    float Kv = K[rS * EDsz + e];
    float dg = delta[rL * EDsz + e];
    float xv = xs[rL * EDsz + e];
    float Yv = Yf[rL * EDsz + e];
    float C0 = __ldg(dC + rL * DCsz + 64);
    float C1 = __ldg(dC + rL * DCsz + 65);
    for (int t = 0; t < SEGsz; t++) {
        float Kn = 0.f, dn = 0.f, xn = 0.f, Yn = 0.f, C0n = 0.f, C1n = 0.f;
        if (t + 1 < SEGsz) {
            Kn  = K[(rS + 1) * EDsz + e];
            dn  = delta[(rL + 1) * EDsz + e];
            xn  = xs[(rL + 1) * EDsz + e];
            Yn  = Yf[(rL + 1) * EDsz + e];
            C0n = __ldg(dC + (rL + 1) * DCsz + 64);
            C1n = __ldg(dC + (rL + 1) * DCsz + 65);
        }
        float Kdy = Kv * Yv;
        {
            float KC = Kv * C0;
            float AmK = A0 * (1.f - KC);
            float Ak  = AmK * (1.f + KC);
            float Bk  = -AmK * Kv;
            float dA  = __expf(dg * Ak);
            h0 = dA * h0 + dg * Bk * xv + Kdy;
        }
        {
            float KC = Kv * C1;
            float AmK = A1 * (1.f - KC);
            float Ak  = AmK * (1.f + KC);
            float Bk  = -AmK * Kv;
            float dA  = __expf(dg * Ak);
            h1 = dA * h1 + dg * Bk * xv + Kdy;
        }
        y[rL * EDsz + e] = h0 * C0 + h1 * C1 + Dpe * xv;
        rL++; rS++;
        Kv = Kn; dg = dn; xv = xn; Yv = Yn; C0 = C0n; C1 = C1n;
    }
}

// ---------------- gate: yg = y * silu(z) -> fp16 (x4) ----------------
__global__ void gate_k(const float* __restrict__ y, const float* __restrict__ xz,
                       __half* __restrict__ gh) {
    size_t idx = (size_t)blockIdx.x * 256 + threadIdx.x;   // B*L*ED/4
    size_t g0 = idx * 4;
    int e = (int)(g0 & (EDsz - 1));
    size_t row = g0 >> 11;
    float4 z = *(const float4*)(xz + row * (2 * EDsz) + EDsz + e);
    float4 yv = *(const float4*)(y + g0);
    float r0 = yv.x * z.x / (1.f + __expf(-z.x));
    float r1 = yv.y * z.y / (1.f + __expf(-z.y));
    float r2 = yv.z * z.z / (1.f + __expf(-z.z));
    float r3 = yv.w * z.w / (1.f + __expf(-z.w));
    *(uint2*)(gh + g0) = pack4h(r0, r1, r2, r3);
}

// ---------------- host ----------------
static float* symAddr(const void* sym) {
    void* p = nullptr;
    cudaGetSymbolAddress(&p, sym);
    return (float*)p;
}
static __half* symAddrH(const void* sym) {
    void* p = nullptr;
    cudaGetSymbolAddress(&p, sym);
    return (__half*)p;
}

extern "C" void kernel_launch(void* const* d_in, const int* in_sizes, int n_in,
                              void* d_out, int out_size) {
    const float* x     = (const float*)d_in[0];
    const float* rms_w = (const float*)d_in[1];
    const float* in_w  = (const float*)d_in[2];
    const float* c1_w  = (const float*)d_in[3];
    const float* c1_b  = (const float*)d_in[4];
    const float* c2_w  = (const float*)d_in[5];
    const float* c2_b  = (const float*)d_in[6];
    const float* xp_w  = (const float*)d_in[7];
    const float* dt_w  = (const float*)d_in[8];
    const float* dt_b  = (const float*)d_in[9];
    const float* A_log = (const float*)d_in[10];
    const float* Dp    = (const float*)d_in[11];
    const float* out_w = (const float*)d_in[12];
    const float* k1_w  = (const float*)d_in[13];
    const float* k1_b  = (const float*)d_in[14];
    const float* k2_w  = (const float*)d_in[15];
    const float* k3_w  = (const float*)d_in[16];
    const float* ln_g  = (const float*)d_in[17];
    const float* ln_b  = (const float*)d_in[18];
    const float* k_al  = (const float*)d_in[19];
    const float* sigma = (const float*)d_in[20];

    float* xz    = symAddr(g_xz);
    float* xs    = symAddr(g_xs);
    float* delta = symAddr(g_delta);
    float* dC    = symAddr(g_dC);
    float* y     = symAddr(g_y);
    float* K     = symAddr(g_K);
    float* h3    = symAddr(g_h3);
    float* Xf    = symAddr(g_Xf);
    float* Zb    = symAddr(g_Zb);
    float* Yf    = symAddr(g_Yf);
    float* dft1  = symAddr(g_dft1);
    float* dft2  = symAddr(g_dft2);
    __half *xnh  = symAddrH(g_xnh);
    __half *inwh = symAddrH(g_inwh);
    __half *xsh  = symAddrH(g_xsh);
    __half *xpwh = symAddrH(g_xpwh);
    __half *keh  = symAddrH(g_keh);
    __half *k1wh = symAddrH(g_k1wh);
    __half *h1h  = symAddrH(g_h1h);
    __half *k2wh = symAddrH(g_k2wh);
    __half *h2h  = symAddrH(g_h2h);
    __half *k3wh = symAddrH(g_k3wh);
    __half *ygh  = symAddrH(g_ygh);
    __half *owh  = symAddrH(g_owh);
    float* h = (float*)d_out;

    const int MROWS = Bsz * Lsz;              // 8192
    const int SROWS = Bsz * SEGsz;            // 1024
    const int NB = Bsz * NSEG;                // 32 FDU batches

    dft_init_k<<<256, 256>>>();
    cudaMemcpyAsync(h, x, sizeof(float) * (size_t)MROWS * DMsz, cudaMemcpyDeviceToDevice);

    for (int i = 0; i < NLsz; i++) {
        const float* rms = rms_w + (size_t)i * DMsz;
        const float* inw = in_w  + (size_t)i * 2 * EDsz * DMsz;
        const float* w1c = c1_w + (size_t)i * EDsz * 2;
        const float* b1c = c1_b + (size_t)i * EDsz;
        const float* w2c = c2_w + (size_t)i * EDsz * 2;
        const float* b2c = c2_b + (size_t)i * EDsz;
        const float* xpw = xp_w + (size_t)i * DCsz * EDsz;
        const float* dtw = dt_w + (size_t)i * EDsz * DTRsz;
        const float* dtb = dt_b + (size_t)i * EDsz;
        const float* alg = A_log + (size_t)i * EDsz * 2;
        const float* dpp = Dp + (size_t)i * EDsz;
        const float* ow  = out_w + (size_t)i * DMsz * EDsz;
        const float* k1w = k1_w + (size_t)i * 3 * EDsz * EDsz;
        const float* k1b = k1_b + (size_t)i * 3 * EDsz;
        const float* k2w = k2_w + (size_t)i * EDsz * 3 * EDsz;
        const float* k3w = k3_w + (size_t)i * EDsz * EDsz;
        const float* lng = ln_g + (size_t)i * EDsz;
        const float* lnb = ln_b + (size_t)i * EDsz;
        const float* kal = k_al + (size_t)i * EDsz;
        const float* sig = sigma + i;

        // weight converts (vectorized x8)
        wconv_k<<<(2*EDsz*DMsz/8 + 255)/256, 256>>>(inw, inwh, 2*EDsz*DMsz/8);
        wconv_k<<<(3*EDsz*EDsz/8 + 255)/256, 256>>>(k1w, k1wh, 3*EDsz*EDsz/8);
        wconv_k<<<(3*EDsz*EDsz/8 + 255)/256, 256>>>(k2w, k2wh, 3*EDsz*EDsz/8);
        wconv_k<<<(EDsz*EDsz/8 + 255)/256, 256>>>(k3w, k3wh, EDsz*EDsz/8);
        wconv_k<<<(DMsz*EDsz/8 + 255)/256, 256>>>(ow, owh, DMsz*EDsz/8);
        xppad_k<<<(128*EDsz/8)/256, 256>>>(xpw, xpwh);

        rmsnorm_k<<<MROWS, 256>>>(h, rms, xnh);

        // xz = xn @ in_w^T   (8192 x 4096, K=1024)
        ts_gemm_k<0,false><<<dim3(32, 64), 256>>>(
            xnh, inwh, xz, nullptr, DMsz, DMsz, 2*EDsz, 2*EDsz, DMsz, nullptr);

        conv_silu_k<<<(MROWS * EDsz / 4) / 256, 256>>>(xz, w1c, b1c, w2c, b2c, xs, xsh);

        // dC = xs @ xp_w^T   (8192 x 66, K=2048) via padded xp_w
        ts_gemm_k<0,false><<<dim3(1, 64), 256>>>(
            xsh, xpwh, dC, nullptr, EDsz, EDsz, DCsz, DCsz, EDsz, nullptr);

        // delta = softplus(dr @ dt_w^T + dt_b)
        gemm_sp_k<<<dim3(16, 64), 256>>>(dC, DCsz, dtw, DTRsz,
                                         delta, EDsz, EDsz, DTRsz, dtb);

        // ----- batched FDU over all 8 segments (hoisted out of seg loop) -----
        // stage 1: [Xr; Xi] = dft1 @ xs_seg   (512 x 2048, K=256, batch=32)
        tgemm_nn_k<<<dim3(16, 4, NB), 256>>>(dft1, SEGsz, 0,
                                             xs, EDsz, (long long)SEGsz * EDsz,
                                             Xf, EDsz, (long long)2 * SEGsz * EDsz, SEGsz);
        czi_k<<<((size_t)NB * SEGsz * EDsz / 4) / 256, 256>>>(Xf, delta, Zb, sig);
        // stage 2: Yf = dft2 @ [Zr; Zi]       (256 x 2048, K=512, batch=32)
        tgemm_nn_k<<<dim3(16, 2, NB), 256>>>(dft2, 2 * SEGsz, 0,
                                             Zb, EDsz, (long long)2 * SEGsz * EDsz,
                                             Yf, EDsz, (long long)SEGsz * EDsz, 2 * SEGsz);

        zero_k<<<(SROWS * EDsz / 4) / 256, 256>>>(K, SROWS * EDsz / 4);

        for (int s = 0; s < NSEG; s++) {
            int s0 = s * SEGsz;

            kerr_k<<<(SROWS * EDsz / 4) / 256, 256>>>(xs, y, keh, s0, s == 0 ? 1 : 0);

            // kproj1: h1 = relu(Kerr @ k1_w^T + b)  (1024 x 6144, K=2048) -> fp16
            ts_gemm_k<1,true><<<dim3(48, 8), 256>>>(
                keh, k1wh, nullptr, h1h, EDsz, EDsz, 3*EDsz, 3*EDsz, EDsz, k1b);
            // kproj2: h2 = relu(h1 @ k2_w^T)        (1024 x 2048, K=6144) -> fp16
            ts_gemm_k<2,true><<<dim3(16, 8), 256>>>(
                h1h, k2wh, nullptr, h2h, 3*EDsz, 3*EDsz, EDsz, EDsz, 3*EDsz, nullptr);
            // kproj3: h3 = h2 @ k3_w^T              (1024 x 2048, K=2048) -> fp32
            ts_gemm_k<0,false><<<dim3(16, 8), 256>>>(
                h2h, k3wh, h3, nullptr, EDsz, EDsz, EDsz, EDsz, EDsz, nullptr);

            kup_k<<<SROWS, 256>>>(h3, lng, lnb, kal, K);

            scan_k<<<Bsz * (EDsz / 64), 64>>>(K, delta, xs, Yf, dC, alg, dpp, y, s0);
        }

        gate_k<<<(MROWS * EDsz / 4) / 256, 256>>>(y, xz, ygh);

        // h += yg @ out_w^T   (8192 x 1024, K=2048)  [accumulate]
        ts_gemm_k<4,false><<<dim3(8, 64), 256>>>(
            ygh, owh, h, nullptr, EDsz, EDsz, DMsz, DMsz, EDsz, nullptr);
    }
}

// round 17
// speedup vs baseline: 1.1500x; 1.0474x over previous
#include <cuda_runtime.h>
#include <cuda_fp16.h>
#include <math.h>
#include <stdint.h>

// ---------------- problem constants ----------------
#define Bsz   4
#define Lsz   2048
#define DMsz  1024
#define EDsz  2048
#define SEGsz 256
#define NSEG  8
#define NLsz  2
#define DTRsz 64
#define DCsz  66   // DTR + N

// ---------------- fp32 scratch ----------------
__device__ float g_xz   [(size_t)Bsz*Lsz*2*EDsz];
__device__ float g_xs   [(size_t)Bsz*Lsz*EDsz];
__device__ float g_delta[(size_t)Bsz*Lsz*EDsz];
__device__ float g_dC   [(size_t)Bsz*Lsz*DCsz];
__device__ float g_y    [(size_t)Bsz*Lsz*EDsz];
__device__ float g_K    [(size_t)Bsz*SEGsz*EDsz];
__device__ float g_h3   [(size_t)Bsz*SEGsz*EDsz];
__device__ float g_Xf   [(size_t)Bsz*NSEG*2*SEGsz*EDsz];
__device__ float g_Zb   [(size_t)Bsz*NSEG*2*SEGsz*EDsz];
__device__ float g_Yf   [(size_t)Bsz*Lsz*EDsz];
__device__ float g_dft1 [2*SEGsz*SEGsz];
__device__ float g_dft2 [SEGsz*2*SEGsz];

// ---------------- fp16 operands ----------------
__device__ __half g_xnh [(size_t)Bsz*Lsz*DMsz];
__device__ __half g_inwh[(size_t)2*EDsz*DMsz];
__device__ __half g_xsh [(size_t)Bsz*Lsz*EDsz];
__device__ __half g_xpwh[(size_t)128*EDsz];
__device__ __half g_keh [(size_t)Bsz*SEGsz*EDsz];
__device__ __half g_k1wh[(size_t)3*EDsz*EDsz];
__device__ __half g_h1h [(size_t)Bsz*SEGsz*3*EDsz];
__device__ __half g_k2wh[(size_t)EDsz*3*EDsz];
__device__ __half g_h2h [(size_t)Bsz*SEGsz*EDsz];
__device__ __half g_k3wh[(size_t)EDsz*EDsz];
__device__ __half g_ygh [(size_t)Bsz*Lsz*EDsz];
__device__ __half g_owh [(size_t)DMsz*EDsz];

// ---------------- small helpers ----------------
__device__ __forceinline__ uint2 pack4h(float a, float b, float c, float d) {
    __half2 h0 = __floats2half2_rn(a, b), h1 = __floats2half2_rn(c, d);
    uint2 u; u.x = *(uint32_t*)&h0; u.y = *(uint32_t*)&h1; return u;
}
__device__ __forceinline__ uint4 pack8h(float4 a, float4 b) {
    __half2 h0 = __floats2half2_rn(a.x, a.y), h1 = __floats2half2_rn(a.z, a.w);
    __half2 h2 = __floats2half2_rn(b.x, b.y), h3 = __floats2half2_rn(b.z, b.w);
    uint4 u; u.x = *(uint32_t*)&h0; u.y = *(uint32_t*)&h1;
    u.z = *(uint32_t*)&h2; u.w = *(uint32_t*)&h3; return u;
}
__device__ __forceinline__ float blkSum(float v) {
    __shared__ float sh[32];
    __syncthreads();
    int lane = threadIdx.x & 31, w = threadIdx.x >> 5;
#pragma unroll
    for (int o = 16; o; o >>= 1) v += __shfl_down_sync(0xffffffffu, v, o);
    if (!lane) sh[w] = v;
    __syncthreads();
    if (w == 0) {
        v = (lane < (int)(blockDim.x >> 5)) ? sh[lane] : 0.f;
#pragma unroll
        for (int o = 16; o; o >>= 1) v += __shfl_down_sync(0xffffffffu, v, o);
        if (!lane) sh[0] = v;
    }
    __syncthreads();
    return sh[0];
}

// ---------------- mma / async primitives ----------------
__device__ __forceinline__ void mma16816(float* d, const uint32_t* a, uint32_t b0, uint32_t b1) {
    asm volatile(
        "mma.sync.aligned.m16n8k16.row.col.f32.f16.f16.f32 "
        "{%0,%1,%2,%3}, {%4,%5,%6,%7}, {%8,%9}, {%0,%1,%2,%3};\n"
        : "+f"(d[0]), "+f"(d[1]), "+f"(d[2]), "+f"(d[3])
        : "r"(a[0]), "r"(a[1]), "r"(a[2]), "r"(a[3]), "r"(b0), "r"(b1));
}
__device__ __forceinline__ void ldsm4(uint32_t* r, uint32_t addr) {
    asm volatile("ldmatrix.sync.aligned.m8n8.x4.shared.b16 {%0,%1,%2,%3}, [%4];\n"
        : "=r"(r[0]), "=r"(r[1]), "=r"(r[2]), "=r"(r[3]) : "r"(addr));
}
__device__ __forceinline__ void cpa16(uint32_t dst, const void* src) {
    asm volatile("cp.async.cg.shared.global [%0], [%1], 16;\n" :: "r"(dst), "l"(src));
}
__device__ __forceinline__ void cpa_commit() { asm volatile("cp.async.commit_group;\n" ::: "memory"); }
template<int N> __device__ __forceinline__ void cpa_wait() {
    asm volatile("cp.async.wait_group %0;\n" :: "n"(N) : "memory");
}

// ================= single-fp16 mma.sync NT GEMM =================
// D = A(MxK) @ B(NxK)^T, fp16 inputs, fp32 accum.
// EPI: 0 none, 1 bias+relu, 2 relu, 4 C += result.  PAIR: emit fp16 output.
#define TS_STAGE 16384
template<int EPI, bool PAIR>
__global__ __launch_bounds__(256) void ts_gemm_k(
    const __half* __restrict__ Ahg, const __half* __restrict__ Bhg,
    float* __restrict__ C, __half* __restrict__ Oh,
    int lda, int ldb, int ldc, int Nn, int K, const float* __restrict__ bias)
{
    __shared__ __align__(16) char sm[2 * TS_STAGE];
    const int tid = threadIdx.x;
    const int lane = tid & 31, wid = tid >> 5;
    const int wm = wid & 1, wn = wid >> 1;
    const int m0 = blockIdx.y * 128, n0 = blockIdx.x * 128;

    float acc[4][4][4];
#pragma unroll
    for (int i = 0; i < 4; i++)
#pragma unroll
        for (int j = 0; j < 4; j++)
#pragma unroll
            for (int q = 0; q < 4; q++) acc[i][j][q] = 0.f;

    const uint32_t smBase = (uint32_t)__cvta_generic_to_shared(sm);
    const int frow0 = tid >> 2;
    const int fc    = tid & 3;
    auto fill = [&](int k0, int st) {
        const uint32_t base = smBase + st * TS_STAGE;
#pragma unroll
        for (int i = 0; i < 2; i++) {
            int row = frow0 + i * 64;
            uint32_t off = (uint32_t)(row * 64 + fc * 16);
            uint32_t dsw = off ^ ((off >> 3) & 0x30);
            cpa16(base +        dsw, Ahg + (size_t)(m0 + row) * lda + k0 + fc * 8);
            cpa16(base + 8192 + dsw, Bhg + (size_t)(n0 + row) * ldb + k0 + fc * 8);
        }
        cpa_commit();
    };

    const int aRow = wm * 64 + (lane & 15);
    const int aCh  = (lane >> 4);
    const int bRow = wn * 32 + (lane & 7) + ((lane & 16) >> 1);
    const int bCh  = ((lane & 8) >> 3);

    const int kt = K >> 5;
    fill(0, 0);
    for (int t = 0; t < kt; t++) {
        if (t + 1 < kt) { fill((t + 1) << 5, (t + 1) & 1); cpa_wait<1>(); }
        else            { cpa_wait<0>(); }
        __syncthreads();
        const uint32_t base = smBase + (t & 1) * TS_STAGE;
#pragma unroll
        for (int ks = 0; ks < 2; ks++) {
            uint32_t bh[2][4];
#pragma unroll
            for (int nt2 = 0; nt2 < 2; nt2++) {
                uint32_t off = (uint32_t)((bRow + nt2 * 16) * 64 + (bCh + ks * 2) * 16);
                uint32_t dsw = off ^ ((off >> 3) & 0x30);
                ldsm4(bh[nt2], base + 8192 + dsw);
            }
#pragma unroll
            for (int mt = 0; mt < 4; mt++) {
                uint32_t off = (uint32_t)((aRow + mt * 16) * 64 + (aCh + ks * 2) * 16);
                uint32_t dsw = off ^ ((off >> 3) & 0x30);
                uint32_t ah[4];
                ldsm4(ah, base + dsw);
#pragma unroll
                for (int n8 = 0; n8 < 4; n8++)
                    mma16816(acc[mt][n8], ah, bh[n8 >> 1][(n8 & 1) * 2], bh[n8 >> 1][(n8 & 1) * 2 + 1]);
            }
        }
        __syncthreads();
    }

    const int g = lane >> 2, cc = (lane & 3) * 2;
#pragma unroll
    for (int mt = 0; mt < 4; mt++) {
        long long m = m0 + wm * 64 + mt * 16 + g;
#pragma unroll
        for (int n8 = 0; n8 < 4; n8++) {
            int col = n0 + wn * 32 + n8 * 8 + cc;
            if (col >= Nn) continue;
            float* a4 = acc[mt][n8];
            float2 v0 = make_float2(a4[0], a4[1]);
            float2 v1 = make_float2(a4[2], a4[3]);
            if (EPI == 1) {
                float b0 = bias[col], b1 = bias[col + 1];
                v0.x = fmaxf(v0.x + b0, 0.f); v0.y = fmaxf(v0.y + b1, 0.f);
                v1.x = fmaxf(v1.x + b0, 0.f); v1.y = fmaxf(v1.y + b1, 0.f);
            } else if (EPI == 2) {
                v0.x = fmaxf(v0.x, 0.f); v0.y = fmaxf(v0.y, 0.f);
                v1.x = fmaxf(v1.x, 0.f); v1.y = fmaxf(v1.y, 0.f);
            }
            if (PAIR) {
                *(__half2*)(Oh + m * ldc + col)       = __floats2half2_rn(v0.x, v0.y);
                *(__half2*)(Oh + (m + 8) * ldc + col) = __floats2half2_rn(v1.x, v1.y);
            } else {
                float* p0 = C + m * ldc + col;
                float* p1 = C + (m + 8) * ldc + col;
                if (EPI == 4) {
                    float2 o0 = *(float2*)p0, o1 = *(float2*)p1;
                    v0.x += o0.x; v0.y += o0.y; v1.x += o1.x; v1.y += o1.y;
                }
                *(float2*)p0 = v0;
                *(float2*)p1 = v1;
            }
        }
    }
}

// ---------------- DFT table init ----------------
__global__ void dft_init_k() {
    int idx = blockIdx.x * 256 + threadIdx.x;
    int t = idx & 255, k = idx >> 8;
    int p = (k * t) & 255;
    float ang = 6.283185307179586f * (float)p * (1.0f / 256.0f);
    float s, c;
    sincosf(ang, &s, &c);
    g_dft1[k * 256 + t]         = c;
    g_dft1[(k + 256) * 256 + t] = -s;
    g_dft2[t * 512 + k]         = c  * (1.0f / 256.0f);
    g_dft2[t * 512 + 256 + k]   = -s * (1.0f / 256.0f);
}

// ---------------- weight convert (fp32 -> fp16), 8 elems/thread ----------------
__global__ void wconv_k(const float* __restrict__ src, __half* __restrict__ dh, int n8) {
    int i = blockIdx.x * 256 + threadIdx.x;
    if (i >= n8) return;
    const float4* s = (const float4*)src + (size_t)i * 2;
    float4 a = s[0], b = s[1];
    *((uint4*)dh + i) = pack8h(a, b);
}
// xp_w padded to 128 rows (rows 66..127 zero), 8 elems/thread
__global__ void xppad_k(const float* __restrict__ src, __half* __restrict__ dh) {
    int i = blockIdx.x * 256 + threadIdx.x;   // 32768 threads
    int g0 = i * 8;
    int row = g0 >> 11, col = g0 & (EDsz - 1);
    float4 a = make_float4(0, 0, 0, 0), b = a;
    if (row < DCsz) {
        a = *(const float4*)(src + (size_t)row * EDsz + col);
        b = *(const float4*)(src + (size_t)row * EDsz + col + 4);
    }
    *((uint4*)dh + i) = pack8h(a, b);
}

// ---------------- RMSNorm -> fp16 (vectorized) ----------------
__global__ void rmsnorm_k(const float* __restrict__ h, const float* __restrict__ w,
                          __half* __restrict__ oh) {
    size_t base = (size_t)blockIdx.x * DMsz;
    int tid = threadIdx.x;                        // 256 threads x 4 = 1024
    float4 v = *((const float4*)(h + base) + tid);
    float s = v.x * v.x + v.y * v.y + v.z * v.z + v.w * v.w;
    s = blkSum(s);
    float r = rsqrtf(s * (1.0f / DMsz) + 1e-5f);
    float4 w4 = *((const float4*)w + tid);
    *((uint2*)(oh + base) + tid) = pack4h(v.x * r * w4.x, v.y * r * w4.y,
                                          v.z * r * w4.z, v.w * r * w4.w);
}

// ---------------- fused double depthwise conv (k=2) + SiLU (x4) ----------------
__global__ void conv_silu_k(const float* __restrict__ xz,
                            const float* __restrict__ c1w, const float* __restrict__ c1b,
                            const float* __restrict__ c2w, const float* __restrict__ c2b,
                            float* __restrict__ xs, __half* __restrict__ xsh) {
    size_t idx = (size_t)blockIdx.x * 256 + threadIdx.x;    // over B*L*ED/4
    size_t g0 = idx * 4;
    int e = (int)(g0 & (EDsz - 1));
    int l = (int)((g0 >> 11) & (Lsz - 1));
    int b = (int)(g0 >> 22);
    const float* base = xz + (size_t)(b * Lsz) * (2 * EDsz) + e;
    float4 x2 = *(const float4*)(base + (size_t)l * (2 * EDsz));
    float4 x1 = (l >= 1) ? *(const float4*)(base + (size_t)(l - 1) * (2 * EDsz)) : make_float4(0,0,0,0);
    float4 x0 = (l >= 2) ? *(const float4*)(base + (size_t)(l - 2) * (2 * EDsz)) : make_float4(0,0,0,0);
    float4 w1a = *(const float4*)(c1w + e * 2);
    float4 w1b = *(const float4*)(c1w + e * 2 + 4);
    float4 w2a = *(const float4*)(c2w + e * 2);
    float4 w2b = *(const float4*)(c2w + e * 2 + 4);
    float4 b1 = *(const float4*)(c1b + e);
    float4 b2 = *(const float4*)(c2b + e);
    float r[4];
    {
        float X0[4] = {x0.x, x0.y, x0.z, x0.w};
        float X1[4] = {x1.x, x1.y, x1.z, x1.w};
        float X2[4] = {x2.x, x2.y, x2.z, x2.w};
        float W10[4] = {w1a.x, w1a.z, w1b.x, w1b.z};
        float W11[4] = {w1a.y, w1a.w, w1b.y, w1b.w};
        float W20[4] = {w2a.x, w2a.z, w2b.x, w2b.z};
        float W21[4] = {w2a.y, w2a.w, w2b.y, w2b.w};
        float B1[4] = {b1.x, b1.y, b1.z, b1.w};
        float B2[4] = {b2.x, b2.y, b2.z, b2.w};
#pragma unroll
        for (int j = 0; j < 4; j++) {
            float y1a = (l >= 1) ? (B1[j] + X0[j] * W10[j] + X1[j] * W11[j]) : 0.f;
            float y1b = B1[j] + X1[j] * W10[j] + X2[j] * W11[j];
            float y2 = B2[j] + y1a * W20[j] + y1b * W21[j];
            r[j] = y2 / (1.f + __expf(-y2));
        }
    }
    *(float4*)(xs + g0) = make_float4(r[0], r[1], r[2], r[3]);
    *(uint2*)(xsh + g0) = pack4h(r[0], r[1], r[2], r[3]);
}

// ---------------- fp16 NN GEMM (FDU, batched): C = A(MxK) @ B(KxN) -------------
__global__ __launch_bounds__(256) void tgemm_nn_k(
    const float* __restrict__ A, int lda, long long sA,
    const float* __restrict__ Bm, int ldb, long long sB,
    float* __restrict__ C, int ldc, long long sC,
    int K)
{
    __shared__ __align__(16) __half Ah[128][40];
    __shared__ __align__(16) __half Bh[128][40];

    const int bz = blockIdx.z;
    A  += (long long)bz * sA;
    Bm += (long long)bz * sB;
    C  += (long long)bz * sC;
    const int m0 = blockIdx.y * 128, n0 = blockIdx.x * 128;
    const int tid = threadIdx.x;
    const int lane = tid & 31, wid = tid >> 5;
    const int wm = wid & 1, wn = wid >> 1;

    float acc[4][4][4];
#pragma unroll
    for (int i = 0; i < 4; i++)
#pragma unroll
        for (int j = 0; j < 4; j++)
#pragma unroll
            for (int q = 0; q < 4; q++) acc[i][j][q] = 0.f;

    const int ak4 = tid & 7;
    const int ar0 = tid >> 3;
    const int bn4 = tid & 31;
    const int bk0 = tid >> 5;

    float4 av[4], bv[4];
    auto loadTile = [&](int k0) {
        const float* pa = A + (long long)(m0 + ar0) * lda + k0 + ak4 * 4;
#pragma unroll
        for (int i = 0; i < 4; i++) av[i] = *(const float4*)(pa + (long long)(32 * i) * lda);
        const float* pb = Bm + (long long)(k0 + bk0) * ldb + n0 + bn4 * 4;
#pragma unroll
        for (int i = 0; i < 4; i++) bv[i] = *(const float4*)(pb + (long long)(8 * i) * ldb);
    };
    auto storeTile = [&]() {
#pragma unroll
        for (int i = 0; i < 4; i++) {
            int row = ar0 + 32 * i;
            float4 v = av[i];
            __half2* dh = (__half2*)&Ah[row][ak4 * 4];
            dh[0] = __floats2half2_rn(v.x, v.y);
            dh[1] = __floats2half2_rn(v.z, v.w);
        }
#pragma unroll
        for (int i = 0; i < 4; i++) {
            int kr = bk0 + 8 * i;
            float4 v = bv[i];
            float s4[4] = {v.x, v.y, v.z, v.w};
#pragma unroll
            for (int j = 0; j < 4; j++)
                Bh[bn4 * 4 + j][kr] = __float2half_rn(s4[j]);
        }
    };

    const uint32_t aBase = (uint32_t)__cvta_generic_to_shared(&Ah[0][0]);
    const uint32_t bBase = (uint32_t)__cvta_generic_to_shared(&Bh[0][0]);
    const uint32_t aOff = ((wm * 64 + (lane & 15)) * 40 + ((lane >> 4) << 3)) * 2;
    const uint32_t bOff = ((wn * 32 + (lane & 7) + ((lane & 16) >> 1)) * 40 + (lane & 8)) * 2;

    const int kt = K >> 5;
    loadTile(0);
    for (int t = 0; t < kt; t++) {
        storeTile();
        __syncthreads();
        if (t + 1 < kt) loadTile((t + 1) << 5);
#pragma unroll
        for (int ks = 0; ks < 2; ks++) {
            uint32_t bhf[2][4];
#pragma unroll
            for (int nt2 = 0; nt2 < 2; nt2++)
                ldsm4(bhf[nt2], bBase + bOff + nt2 * 16 * 80 + ks * 32);
#pragma unroll
            for (int mt = 0; mt < 4; mt++) {
                uint32_t ahf[4];
                ldsm4(ahf, aBase + aOff + mt * 16 * 80 + ks * 32);
#pragma unroll
                for (int n8 = 0; n8 < 4; n8++)
                    mma16816(acc[mt][n8], ahf, bhf[n8 >> 1][(n8 & 1) * 2], bhf[n8 >> 1][(n8 & 1) * 2 + 1]);
            }
        }
        __syncthreads();
    }

    const int g = lane >> 2, cc = (lane & 3) * 2;
#pragma unroll
    for (int mt = 0; mt < 4; mt++) {
        long long m = m0 + wm * 64 + mt * 16 + g;
#pragma unroll
        for (int n8 = 0; n8 < 4; n8++) {
            int col = n0 + wn * 32 + n8 * 8 + cc;
            float* a4 = acc[mt][n8];
            *(float2*)(C + m * ldc + col)       = make_float2(a4[0], a4[1]);
            *(float2*)(C + (m + 8) * ldc + col) = make_float2(a4[2], a4[3]);
        }
    }
}

// ---------------- SIMT fp32 GEMM (delta only: bias+softplus) ----------------
__global__ __launch_bounds__(256) void gemm_sp_k(
    const float* __restrict__ A, int lda,
    const float* __restrict__ Bm, int ldb,
    float* __restrict__ C, int ldc,
    int N, int K, const float* __restrict__ bias)
{
    __shared__ float As[16][128];
    __shared__ float Bs[16][132];
    const int m0 = blockIdx.y * 128, n0 = blockIdx.x * 128;
    const int tid = threadIdx.x;
    const int tx = tid & 15, ty = tid >> 4;
    float acc[8][8];
#pragma unroll
    for (int i = 0; i < 8; i++)
#pragma unroll
        for (int j = 0; j < 8; j++) acc[i][j] = 0.f;
    const bool a4 = ((lda & 3) == 0);

    for (int k0 = 0; k0 < K; k0 += 16) {
        {
            int r = tid >> 2, c4 = (tid & 3) << 2;
#pragma unroll
            for (int rr = 0; rr < 2; rr++) {
                int row = r + rr * 64;
                const float* p = A + (long long)(m0 + row) * lda + (k0 + c4);
                float4 v;
                if (a4) v = *(const float4*)p;
                else { v.x = p[0]; v.y = p[1]; v.z = p[2]; v.w = p[3]; }
                As[c4 + 0][row] = v.x; As[c4 + 1][row] = v.y;
                As[c4 + 2][row] = v.z; As[c4 + 3][row] = v.w;
            }
        }
        {
            int r = tid >> 2, c4 = (tid & 3) << 2;
#pragma unroll
            for (int rr = 0; rr < 2; rr++) {
                int row = r + rr * 64;
                float4 v = make_float4(0.f, 0.f, 0.f, 0.f);
                if (n0 + row < N) {
                    const float* p = Bm + (long long)(n0 + row) * ldb + (k0 + c4);
                    v.x = p[0]; v.y = p[1]; v.z = p[2]; v.w = p[3];
                }
                Bs[c4 + 0][row] = v.x; Bs[c4 + 1][row] = v.y;
                Bs[c4 + 2][row] = v.z; Bs[c4 + 3][row] = v.w;
            }
        }
        __syncthreads();
#pragma unroll
        for (int kk = 0; kk < 16; kk++) {
            float a[8], b[8];
            *(float4*)&a[0] = *(const float4*)&As[kk][ty * 8];
            *(float4*)&a[4] = *(const float4*)&As[kk][ty * 8 + 4];
            *(float4*)&b[0] = *(const float4*)&Bs[kk][tx * 8];
            *(float4*)&b[4] = *(const float4*)&Bs[kk][tx * 8 + 4];
#pragma unroll
            for (int i = 0; i < 8; i++)
#pragma unroll
                for (int j = 0; j < 8; j++)
                    acc[i][j] = fmaf(a[i], b[j], acc[i][j]);
        }
        __syncthreads();
    }
#pragma unroll
    for (int ii = 0; ii < 8; ii++) {
        long long m = m0 + ty * 8 + ii;
        float* Crow = C + m * (long long)ldc;
#pragma unroll
        for (int jj = 0; jj < 8; jj++) {
            int n = n0 + tx * 8 + jj;
            if (n >= N) continue;
            float v = acc[ii][jj] + bias[n];
            Crow[n] = (v > 20.f) ? v : log1pf(expf(v));
        }
    }
}

// ---------------- zero fill (x4) ----------------
__global__ void zero_k(float* p, int n4) {
    int i = blockIdx.x * 256 + threadIdx.x;
    if (i < n4) ((float4*)p)[i] = make_float4(0, 0, 0, 0);
}

// ---------------- Kerr = softsign((xg - yh)^2) -> fp16 (x4) ----------------
__global__ void kerr_k(const float* __restrict__ xs, const float* __restrict__ y,
                       __half* __restrict__ kh, int s0, int first) {
    size_t idx = (size_t)blockIdx.x * 256 + threadIdx.x;   // B*SEG*ED/4
    size_t g0 = idx * 4;
    int e = (int)(g0 & (EDsz - 1));
    int t = (int)((g0 >> 11) & (SEGsz - 1));
    int b = (int)(g0 >> 19);
    float4 xg = *(const float4*)(xs + ((size_t)(b * Lsz + s0 + t)) * EDsz + e);
    float4 yh = make_float4(0, 0, 0, 0);
    if (!first) yh = *(const float4*)(y + ((size_t)(b * Lsz + s0 - SEGsz + t)) * EDsz + e);
    float r[4];
    float dx[4] = {xg.x - yh.x, xg.y - yh.y, xg.z - yh.z, xg.w - yh.w};
#pragma unroll
    for (int j = 0; j < 4; j++) { float d = dx[j] * dx[j]; r[j] = d / (1.f + d); }
    *(uint2*)(kh + g0) = pack4h(r[0], r[1], r[2], r[3]);
}

// ---------------- LayerNorm(h3) -> Knew; K = (1-a)K + a*Knew (x8) ----------------
__global__ void kup_k(const float* __restrict__ h3,
                      const float* __restrict__ lng, const float* __restrict__ lnb,
                      const float* __restrict__ kal, float* __restrict__ K) {
    size_t base = (size_t)blockIdx.x * EDsz;
    int e0 = threadIdx.x * 8;
    float4 va = *(const float4*)(h3 + base + e0);
    float4 vb = *(const float4*)(h3 + base + e0 + 4);
    float v[8] = {va.x, va.y, va.z, va.w, vb.x, vb.y, vb.z, vb.w};
    float s = 0.f;
#pragma unroll
    for (int j = 0; j < 8; j++) s += v[j];
    s = blkSum(s);
    float mu = s * (1.0f / EDsz);
    float q = 0.f;
#pragma unroll
    for (int j = 0; j < 8; j++) { float d = v[j] - mu; q += d * d; }
    q = blkSum(q);
    float rstd = rsqrtf(q * (1.0f / EDsz) + 1e-5f);
    float4 ga = *(const float4*)(lng + e0), gb = *(const float4*)(lng + e0 + 4);
    float4 ba = *(const float4*)(lnb + e0), bb = *(const float4*)(lnb + e0 + 4);
    float4 aa = *(const float4*)(kal + e0), ab = *(const float4*)(kal + e0 + 4);
    float4 ka = *(const float4*)(K + base + e0), kb = *(const float4*)(K + base + e0 + 4);
    float gv[8] = {ga.x, ga.y, ga.z, ga.w, gb.x, gb.y, gb.z, gb.w};
    float bv[8] = {ba.x, ba.y, ba.z, ba.w, bb.x, bb.y, bb.z, bb.w};
    float av2[8] = {aa.x, aa.y, aa.z, aa.w, ab.x, ab.y, ab.z, ab.w};
    float kv[8] = {ka.x, ka.y, ka.z, ka.w, kb.x, kb.y, kb.z, kb.w};
#pragma unroll
    for (int j = 0; j < 8; j++) {
        float kn = gv[j] * (v[j] - mu) * rstd + bv[j];
        float a = fminf(fmaxf(av2[j], 0.01f), 0.99f);
        kv[j] = (1.f - a) * kv[j] + a * kn;
    }
    *(float4*)(K + base + e0)     = make_float4(kv[0], kv[1], kv[2], kv[3]);
    *(float4*)(K + base + e0 + 4) = make_float4(kv[4], kv[5], kv[6], kv[7]);
}

// ---------------- FDU middle: Z = i*c scaling (batched over B*NSEG, x4) ---------
__global__ void czi_k(const float* __restrict__ Xf, const float* __restrict__ delta,
                      float* __restrict__ Z, const float* __restrict__ sigp) {
    size_t idx = (size_t)blockIdx.x * 256 + threadIdx.x;   // B*NSEG*SEG*ED/4
    size_t g0 = idx * 4;
    int e = (int)(g0 & (EDsz - 1));
    int k = (int)((g0 >> 11) & (SEGsz - 1));
    int z = (int)(g0 >> 19);
    float sig = sigp[0];
    float f = (float)((k < 128) ? k : k - 256) * (1.0f / 256.0f);
    float gk = __expf(-f * f * sig * sig);
    float w = 6.283185307179586f * f * gk;
    float4 dt = *(const float4*)(delta + ((size_t)z * SEGsz + k) * EDsz + e);
    size_t base = ((size_t)z * 2 * SEGsz + k) * EDsz + e;
    float4 xr = *(const float4*)(Xf + base);
    float4 xi = *(const float4*)(Xf + base + (size_t)SEGsz * EDsz);
    float c0 = w / (dt.x + 1e-5f), c1 = w / (dt.y + 1e-5f);
    float c2 = w / (dt.z + 1e-5f), c3 = w / (dt.w + 1e-5f);
    *(float4*)(Z + base) = make_float4(-c0 * xi.x, -c1 * xi.y, -c2 * xi.z, -c3 * xi.w);
    *(float4*)(Z + base + (size_t)SEGsz * EDsz) = make_float4(c0 * xr.x, c1 * xr.y, c2 * xr.z, c3 * xr.w);
}

// ---------------- segment scan (software prefetch, 128-thread blocks) -----------
__global__ void scan_k(const float* __restrict__ K, const float* __restrict__ delta,
                       const float* __restrict__ xs, const float* __restrict__ Yf,
                       const float* __restrict__ dC, const float* __restrict__ Alog,
                       const float* __restrict__ Dpv, float* __restrict__ y, int s0) {
    int b = blockIdx.x >> 4;
    int e = ((blockIdx.x & 15) << 7) + threadIdx.x;
    float A0 = -__expf(Alog[e * 2 + 0]);
    float A1 = -__expf(Alog[e * 2 + 1]);
    float Dpe = Dpv[e];
    float h0 = 0.f, h1 = 0.f;
    size_t rL = (size_t)(b * Lsz + s0);
    size_t rS = (size_t)(b * SEGsz);
    float Kv = K[rS * EDsz + e];
    float dg = delta[rL * EDsz + e];
    float xv = xs[rL * EDsz + e];
    float Yv = Yf[rL * EDsz + e];
    float C0 = __ldg(dC + rL * DCsz + 64);
    float C1 = __ldg(dC + rL * DCsz + 65);
    for (int t = 0; t < SEGsz; t++) {
        float Kn = 0.f, dn = 0.f, xn = 0.f, Yn = 0.f, C0n = 0.f, C1n = 0.f;
        if (t + 1 < SEGsz) {
            Kn  = K[(rS + 1) * EDsz + e];
            dn  = delta[(rL + 1) * EDsz + e];
            xn  = xs[(rL + 1) * EDsz + e];
            Yn  = Yf[(rL + 1) * EDsz + e];
            C0n = __ldg(dC + (rL + 1) * DCsz + 64);
            C1n = __ldg(dC + (rL + 1) * DCsz + 65);
        }
        float Kdy = Kv * Yv;
        {
            float KC = Kv * C0;
            float AmK = A0 * (1.f - KC);
            float Ak  = AmK * (1.f + KC);
            float Bk  = -AmK * Kv;
            float dA  = __expf(dg * Ak);
            h0 = dA * h0 + dg * Bk * xv + Kdy;
        }
        {
            float KC = Kv * C1;
            float AmK = A1 * (1.f - KC);
            float Ak  = AmK * (1.f + KC);
            float Bk  = -AmK * Kv;
            float dA  = __expf(dg * Ak);
            h1 = dA * h1 + dg * Bk * xv + Kdy;
        }
        y[rL * EDsz + e] = h0 * C0 + h1 * C1 + Dpe * xv;
        rL++; rS++;
        Kv = Kn; dg = dn; xv = xn; Yv = Yn; C0 = C0n; C1 = C1n;
    }
}

// ---------------- gate: yg = y * silu(z) -> fp16 (x4) ----------------
__global__ void gate_k(const float* __restrict__ y, const float* __restrict__ xz,
                       __half* __restrict__ gh) {
    size_t idx = (size_t)blockIdx.x * 256 + threadIdx.x;   // B*L*ED/4
    size_t g0 = idx * 4;
    int e = (int)(g0 & (EDsz - 1));
    size_t row = g0 >> 11;
    float4 z = *(const float4*)(xz + row * (2 * EDsz) + EDsz + e);
    float4 yv = *(const float4*)(y + g0);
    float r0 = yv.x * z.x / (1.f + __expf(-z.x));
    float r1 = yv.y * z.y / (1.f + __expf(-z.y));
    float r2 = yv.z * z.z / (1.f + __expf(-z.z));
    float r3 = yv.w * z.w / (1.f + __expf(-z.w));
    *(uint2*)(gh + g0) = pack4h(r0, r1, r2, r3);
}

// ---------------- host ----------------
static float* symAddr(const void* sym) {
    void* p = nullptr;
    cudaGetSymbolAddress(&p, sym);
    return (float*)p;
}
static __half* symAddrH(const void* sym) {
    void* p = nullptr;
    cudaGetSymbolAddress(&p, sym);
    return (__half*)p;
}

extern "C" void kernel_launch(void* const* d_in, const int* in_sizes, int n_in,
                              void* d_out, int out_size) {
    const float* x     = (const float*)d_in[0];
    const float* rms_w = (const float*)d_in[1];
    const float* in_w  = (const float*)d_in[2];
    const float* c1_w  = (const float*)d_in[3];
    const float* c1_b  = (const float*)d_in[4];
    const float* c2_w  = (const float*)d_in[5];
    const float* c2_b  = (const float*)d_in[6];
    const float* xp_w  = (const float*)d_in[7];
    const float* dt_w  = (const float*)d_in[8];
    const float* dt_b  = (const float*)d_in[9];
    const float* A_log = (const float*)d_in[10];
    const float* Dp    = (const float*)d_in[11];
    const float* out_w = (const float*)d_in[12];
    const float* k1_w  = (const float*)d_in[13];
    const float* k1_b  = (const float*)d_in[14];
    const float* k2_w  = (const float*)d_in[15];
    const float* k3_w  = (const float*)d_in[16];
    const float* ln_g  = (const float*)d_in[17];
    const float* ln_b  = (const float*)d_in[18];
    const float* k_al  = (const float*)d_in[19];
    const float* sigma = (const float*)d_in[20];

    float* xz    = symAddr(g_xz);
    float* xs    = symAddr(g_xs);
    float* delta = symAddr(g_delta);
    float* dC    = symAddr(g_dC);
    float* y     = symAddr(g_y);
    float* K     = symAddr(g_K);
    float* h3    = symAddr(g_h3);
    float* Xf    = symAddr(g_Xf);
    float* Zb    = symAddr(g_Zb);
    float* Yf    = symAddr(g_Yf);
    float* dft1  = symAddr(g_dft1);
    float* dft2  = symAddr(g_dft2);
    __half *xnh  = symAddrH(g_xnh);
    __half *inwh = symAddrH(g_inwh);
    __half *xsh  = symAddrH(g_xsh);
    __half *xpwh = symAddrH(g_xpwh);
    __half *keh  = symAddrH(g_keh);
    __half *k1wh = symAddrH(g_k1wh);
    __half *h1h  = symAddrH(g_h1h);
    __half *k2wh = symAddrH(g_k2wh);
    __half *h2h  = symAddrH(g_h2h);
    __half *k3wh = symAddrH(g_k3wh);
    __half *ygh  = symAddrH(g_ygh);
    __half *owh  = symAddrH(g_owh);
    float* h = (float*)d_out;

    // streams/events for fork-join overlap (host objects, created once)
    static cudaStream_t s1 = nullptr;
    static cudaEvent_t evStart[NLsz], evW1[NLsz], evW2[NLsz], evConv[NLsz], evFDU[NLsz];
    if (!s1) {
        cudaStreamCreateWithFlags(&s1, cudaStreamNonBlocking);
        for (int i = 0; i < NLsz; i++) {
            cudaEventCreateWithFlags(&evStart[i], cudaEventDisableTiming);
            cudaEventCreateWithFlags(&evW1[i],    cudaEventDisableTiming);
            cudaEventCreateWithFlags(&evW2[i],    cudaEventDisableTiming);
            cudaEventCreateWithFlags(&evConv[i],  cudaEventDisableTiming);
            cudaEventCreateWithFlags(&evFDU[i],   cudaEventDisableTiming);
        }
    }

    const int MROWS = Bsz * Lsz;              // 8192
    const int SROWS = Bsz * SEGsz;            // 1024
    const int NB = Bsz * NSEG;                // 32 FDU batches

    dft_init_k<<<256, 256>>>();
    cudaMemcpyAsync(h, x, sizeof(float) * (size_t)MROWS * DMsz, cudaMemcpyDeviceToDevice);

    for (int i = 0; i < NLsz; i++) {
        const float* rms = rms_w + (size_t)i * DMsz;
        const float* inw = in_w  + (size_t)i * 2 * EDsz * DMsz;
        const float* w1c = c1_w + (size_t)i * EDsz * 2;
        const float* b1c = c1_b + (size_t)i * EDsz;
        const float* w2c = c2_w + (size_t)i * EDsz * 2;
        const float* b2c = c2_b + (size_t)i * EDsz;
        const float* xpw = xp_w + (size_t)i * DCsz * EDsz;
        const float* dtw = dt_w + (size_t)i * EDsz * DTRsz;
        const float* dtb = dt_b + (size_t)i * EDsz;
        const float* alg = A_log + (size_t)i * EDsz * 2;
        const float* dpp = Dp + (size_t)i * EDsz;
        const float* ow  = out_w + (size_t)i * DMsz * EDsz;
        const float* k1w = k1_w + (size_t)i * 3 * EDsz * EDsz;
        const float* k1b = k1_b + (size_t)i * 3 * EDsz;
        const float* k2w = k2_w + (size_t)i * EDsz * 3 * EDsz;
        const float* k3w = k3_w + (size_t)i * EDsz * EDsz;
        const float* lng = ln_g + (size_t)i * EDsz;
        const float* lnb = ln_b + (size_t)i * EDsz;
        const float* kal = k_al + (size_t)i * EDsz;
        const float* sig = sigma + i;

        // fork aux stream at layer start
        cudaEventRecord(evStart[i], 0);
        cudaStreamWaitEvent(s1, evStart[i], 0);

        // s1: weight converts (inw first — gates in-proj), then the rest
        wconv_k<<<(2*EDsz*DMsz/8 + 255)/256, 256, 0, s1>>>(inw, inwh, 2*EDsz*DMsz/8);
        cudaEventRecord(evW1[i], s1);
        wconv_k<<<(3*EDsz*EDsz/8 + 255)/256, 256, 0, s1>>>(k1w, k1wh, 3*EDsz*EDsz/8);
        wconv_k<<<(3*EDsz*EDsz/8 + 255)/256, 256, 0, s1>>>(k2w, k2wh, 3*EDsz*EDsz/8);
        wconv_k<<<(EDsz*EDsz/8 + 255)/256, 256, 0, s1>>>(k3w, k3wh, EDsz*EDsz/8);
        wconv_k<<<(DMsz*EDsz/8 + 255)/256, 256, 0, s1>>>(ow, owh, DMsz*EDsz/8);
        xppad_k<<<(128*EDsz/8)/256, 256, 0, s1>>>(xpw, xpwh);
        cudaEventRecord(evW2[i], s1);

        // s0: rmsnorm (independent of weight converts)
        rmsnorm_k<<<MROWS, 256>>>(h, rms, xnh);

        // s0: in-proj needs inwh
        cudaStreamWaitEvent(0, evW1[i], 0);
        ts_gemm_k<0,false><<<dim3(32, 64), 256>>>(
            xnh, inwh, xz, nullptr, DMsz, DMsz, 2*EDsz, 2*EDsz, DMsz, nullptr);

        conv_silu_k<<<(MROWS * EDsz / 4) / 256, 256>>>(xz, w1c, b1c, w2c, b2c, xs, xsh);
        cudaEventRecord(evConv[i], 0);

        // ----- s1 branch: dC -> delta -> FDU (only scan needs these) -----
        cudaStreamWaitEvent(s1, evConv[i], 0);
        // FDU stage 1 needs only xs
        tgemm_nn_k<<<dim3(16, 4, NB), 256, 0, s1>>>(dft1, SEGsz, 0,
                                             xs, EDsz, (long long)SEGsz * EDsz,
                                             Xf, EDsz, (long long)2 * SEGsz * EDsz, SEGsz);
        // dC = xs @ xp_w^T (xpwh ordered on s1 via program order)
        ts_gemm_k<0,false><<<dim3(1, 64), 256, 0, s1>>>(
            xsh, xpwh, dC, nullptr, EDsz, EDsz, DCsz, DCsz, EDsz, nullptr);
        // delta = softplus(...)
        gemm_sp_k<<<dim3(16, 64), 256, 0, s1>>>(dC, DCsz, dtw, DTRsz,
                                         delta, EDsz, EDsz, DTRsz, dtb);
        czi_k<<<((size_t)NB * SEGsz * EDsz / 4) / 256, 256, 0, s1>>>(Xf, delta, Zb, sig);
        tgemm_nn_k<<<dim3(16, 2, NB), 256, 0, s1>>>(dft2, 2 * SEGsz, 0,
                                             Zb, EDsz, (long long)2 * SEGsz * EDsz,
                                             Yf, EDsz, (long long)SEGsz * EDsz, 2 * SEGsz);
        cudaEventRecord(evFDU[i], s1);

        // ----- s0 branch: K init, kerr(0), kproj chain(0), kup(0) -----
        zero_k<<<(SROWS * EDsz / 4) / 256, 256>>>(K, SROWS * EDsz / 4);
        kerr_k<<<(SROWS * EDsz / 4) / 256, 256>>>(xs, y, keh, 0, 1);
        cudaStreamWaitEvent(0, evW2[i], 0);   // kproj needs k1wh/k2wh/k3wh

        for (int s = 0; s < NSEG; s++) {
            int s0v = s * SEGsz;
            if (s > 0)
                kerr_k<<<(SROWS * EDsz / 4) / 256, 256>>>(xs, y, keh, s0v, 0);

            ts_gemm_k<1,true><<<dim3(48, 8), 256>>>(
                keh, k1wh, nullptr, h1h, EDsz, EDsz, 3*EDsz, 3*EDsz, EDsz, k1b);
            ts_gemm_k<2,true><<<dim3(16, 8), 256>>>(
                h1h, k2wh, nullptr, h2h, 3*EDsz, 3*EDsz, EDsz, EDsz, 3*EDsz, nullptr);
            ts_gemm_k<0,false><<<dim3(16, 8), 256>>>(
                h2h, k3wh, h3, nullptr, EDsz, EDsz, EDsz, EDsz, EDsz, nullptr);

            kup_k<<<SROWS, 256>>>(h3, lng, lnb, kal, K);

            if (s == 0) cudaStreamWaitEvent(0, evFDU[i], 0);   // join delta/Yf/dC
            scan_k<<<Bsz * (EDsz / 128), 128>>>(K, delta, xs, Yf, dC, alg, dpp, y, s0v);
        }

        gate_k<<<(MROWS * EDsz / 4) / 256, 256>>>(y, xz, ygh);

        // h += yg @ out_w^T   (8192 x 1024, K=2048)  [accumulate]
        ts_gemm_k<4,false><<<dim3(8, 64), 256>>>(
            ygh, owh, h, nullptr, EDsz, EDsz, DMsz, DMsz, EDsz, nullptr);
    }
}